// round 15
// baseline (speedup 1.0000x reference)
#include <cuda_runtime.h>
#include <cuda_fp16.h>
#include <math.h>

// ---------------- problem constants ----------------
#define BATCH 64
#define TLAT  249
#define NCODE 1024
#define NBOOK 8

#define X_OUT_SZ   (64*119688)          // 7660032
#define CODES_SZ   (64*8*249)           // 127488
#define FULL_OUT   (X_OUT_SZ + CODES_SZ + 1)

#define D3_LIN  14961
#define D3_LOUT 119688

// ---------------- scratch (static device globals; no allocs) ----------------
__device__ float g_bufA[61440000];
__device__ float g_bufB[122552320];
__device__ float g_z  [BATCH*512*TLAT];
__device__ float g_res[BATCH*512*TLAT];
__device__ float g_zp [BATCH*128*TLAT];
__device__ float g_zq [BATCH*128*TLAT];
__device__ float g_wt [512*256*6];
__device__ int   g_codes[BATCH*NBOOK*TLAT];
__device__ float g_cnorm[NBOOK*NCODE];
__device__ float g_cnmax[NBOOK];
__device__ float g_part[NBOOK*63];
__device__ float g_ps2[8*64*256*2];
__device__ int   g_pi2[8*64*256*2];

// ====================================================================
// BIG GEMM (scalar fp32, bitwise-stable sequential-k chain) — encoder
// + RVQ proj GEMMs. This path must remain bit-exact (argmin ties).
//   EPI 0: store ; 1: +bias ; 2: snake ; 3: Out -= (acc+bias)
//   EPI 4: Out = Z2 - (acc+bias)
// ====================================================================
template<int XMODE, int EPI, int KK, int SS, int PP>
__global__ void __launch_bounds__(256, 2) gemm_big_k(
    const float* __restrict__ A, const float* __restrict__ X,
    const float* __restrict__ bias, const float* __restrict__ Z2,
    const float* __restrict__ alpha,
    float* __restrict__ Out,
    int M, int K, int N, int Lin, int Cin)
{
    __shared__ __align__(16) float As[2][16][128];
    __shared__ __align__(16) float Xs[2][16][128];
    const int tid = threadIdx.x;
    const int n0 = blockIdx.x * 128;
    const int m0 = blockIdx.y * 128;
    const int b  = blockIdx.z;
    const int mi = tid >> 4;
    const int ni = tid & 15;

    const int a_row = tid >> 1;
    const int a_k   = (tid & 1) * 8;
    const int x_row = tid >> 4;
    const int x_col = tid & 15;

    float acc[8][8];
#pragma unroll
    for (int i = 0; i < 8; i++)
#pragma unroll
        for (int j = 0; j < 8; j++) acc[i][j] = 0.f;

    float ar[8], xr[8];

    auto loadA = [&](int k0) {
        const float* ap = A + (size_t)(m0 + a_row) * K + (k0 + a_k);
        float4 v0 = *reinterpret_cast<const float4*>(ap);
        float4 v1 = *reinterpret_cast<const float4*>(ap + 4);
        ar[0]=v0.x; ar[1]=v0.y; ar[2]=v0.z; ar[3]=v0.w;
        ar[4]=v1.x; ar[5]=v1.y; ar[6]=v1.z; ar[7]=v1.w;
    };
    auto loadX = [&](int k0) {
        int kidx = k0 + x_row;
        if constexpr (XMODE == 0) {
            const float* xrow = X + ((size_t)b * K + kidx) * N;
#pragma unroll
            for (int c = 0; c < 8; c++) {
                int n = n0 + x_col + 16 * c;
                xr[c] = (n < N) ? xrow[n] : 0.f;
            }
        } else {
            int ci = kidx / KK;
            int jj = kidx - ci * KK;
            const float* xrow = X + ((size_t)b * Cin + ci) * Lin;
#pragma unroll
            for (int c = 0; c < 8; c++) {
                int n = n0 + x_col + 16 * c;
                int x = n * SS - PP + jj;
                xr[c] = (x >= 0 && x < Lin) ? xrow[x] : 0.f;
            }
        }
    };

    loadA(0);
    loadX(0);
#pragma unroll
    for (int c = 0; c < 8; c++) As[0][a_k + c][a_row] = ar[c];
#pragma unroll
    for (int c = 0; c < 8; c++) Xs[0][x_row][x_col + 16 * c] = xr[c];
    __syncthreads();

    int pb = 0;
    for (int k0 = 0; k0 < K; k0 += 16) {
        const bool more = (k0 + 16 < K);
        if (more) { loadA(k0 + 16); loadX(k0 + 16); }

#pragma unroll
        for (int kk = 0; kk < 16; kk++) {
            const float4* Ap = reinterpret_cast<const float4*>(&As[pb][kk][mi * 8]);
            const float4* Xp = reinterpret_cast<const float4*>(&Xs[pb][kk][ni * 8]);
            float4 a0 = Ap[0], a1 = Ap[1];
            float4 x0 = Xp[0], x1 = Xp[1];
            float av[8] = {a0.x,a0.y,a0.z,a0.w,a1.x,a1.y,a1.z,a1.w};
            float xv[8] = {x0.x,x0.y,x0.z,x0.w,x1.x,x1.y,x1.z,x1.w};
#pragma unroll
            for (int i = 0; i < 8; i++)
#pragma unroll
                for (int j = 0; j < 8; j++)
                    acc[i][j] = fmaf(av[i], xv[j], acc[i][j]);
        }

        if (more) {
            int nb = pb ^ 1;
#pragma unroll
            for (int c = 0; c < 8; c++) As[nb][a_k + c][a_row] = ar[c];
#pragma unroll
            for (int c = 0; c < 8; c++) Xs[nb][x_row][x_col + 16 * c] = xr[c];
            __syncthreads();
            pb = nb;
        }
    }

#pragma unroll
    for (int i = 0; i < 8; i++) {
        int m = m0 + mi * 8 + i;
        float bv = 0.f, al = 1.f;
        if constexpr (EPI != 0) bv = bias[m];
        if constexpr (EPI == 2) al = alpha[m];
#pragma unroll
        for (int j = 0; j < 8; j++) {
            int n = n0 + ni * 8 + j;
            if (n >= N) continue;
            size_t o = ((size_t)b * M + m) * N + n;
            float v = __fadd_rn(acc[i][j], bv);
            if constexpr (EPI == 2) {
                float s = sinf(al * v);
                v = v + s * s / al;
            }
            if constexpr (EPI == 3)      Out[o] = __fadd_rn(Out[o], -v);
            else if constexpr (EPI == 4) Out[o] = __fadd_rn(Z2[o], -v);
            else                         Out[o] = v;
        }
    }
}

// ====================================================================
// Small GEMM (64x64x16, 4x4) — only for E0 (M=64, K=16).
// ====================================================================
template<int XMODE, int EPI, int KK, int SS, int PP>
__global__ void __launch_bounds__(256) gemm_k(
    const float* __restrict__ A, const float* __restrict__ X,
    const float* __restrict__ bias, const float* __restrict__ alpha,
    float* __restrict__ Out,
    int M, int K, int N, int Lin, int Cin)
{
    __shared__ __align__(16) float As[16][64];
    __shared__ __align__(16) float Xs[16][64];
    const int tid = threadIdx.x;
    const int n0 = blockIdx.x * 64;
    const int m0 = blockIdx.y * 64;
    const int b  = blockIdx.z;
    const int mi = tid >> 4, ni = tid & 15;

    float acc[4][4];
#pragma unroll
    for (int i = 0; i < 4; i++)
#pragma unroll
        for (int j = 0; j < 4; j++) acc[i][j] = 0.f;

    const int a_row  = tid >> 2;
    const int a_quad = (tid & 3) * 4;
    const int x_kk   = tid >> 4;
    const int x_j    = (tid & 15) * 4;

    for (int k0 = 0; k0 < K; k0 += 16) {
        float4 av4 = make_float4(0.f, 0.f, 0.f, 0.f);
        if (m0 + a_row < M)
            av4 = *reinterpret_cast<const float4*>(
                      A + (size_t)(m0 + a_row) * K + k0 + a_quad);
        As[a_quad + 0][a_row] = av4.x;
        As[a_quad + 1][a_row] = av4.y;
        As[a_quad + 2][a_row] = av4.z;
        As[a_quad + 3][a_row] = av4.w;

        if constexpr (XMODE == 0) {
            const float* xrow = X + ((size_t)b * K + (k0 + x_kk)) * N;
#pragma unroll
            for (int c = 0; c < 4; c++) {
                int n = n0 + x_j + c;
                Xs[x_kk][x_j + c] = (n < N) ? xrow[n] : 0.f;
            }
        } else {
            int kidx = k0 + x_kk;
            int ci   = kidx / KK;
            int jj   = kidx - ci * KK;
            const float* xrow = X + ((size_t)b * Cin + ci) * Lin;
#pragma unroll
            for (int c = 0; c < 4; c++) {
                int n = n0 + x_j + c;
                int x = n * SS - PP + jj;
                Xs[x_kk][x_j + c] = (x >= 0 && x < Lin) ? xrow[x] : 0.f;
            }
        }
        __syncthreads();

#pragma unroll
        for (int kk = 0; kk < 16; kk++) {
            float4 a4 = *reinterpret_cast<const float4*>(&As[kk][mi * 4]);
            float4 x4 = *reinterpret_cast<const float4*>(&Xs[kk][ni * 4]);
            float av[4] = {a4.x, a4.y, a4.z, a4.w};
            float xv[4] = {x4.x, x4.y, x4.z, x4.w};
#pragma unroll
            for (int i = 0; i < 4; i++)
#pragma unroll
                for (int j = 0; j < 4; j++)
                    acc[i][j] = fmaf(av[i], xv[j], acc[i][j]);
        }
        __syncthreads();
    }

#pragma unroll
    for (int i = 0; i < 4; i++) {
        int m = m0 + mi * 4 + i;
        if (m >= M) continue;
        float bv = 0.f, al = 1.f;
        if constexpr (EPI != 0) bv = bias[m];
        if constexpr (EPI == 2) al = alpha[m];
#pragma unroll
        for (int j = 0; j < 4; j++) {
            int n = n0 + ni * 4 + j;
            if (n >= N) continue;
            size_t o = ((size_t)b * M + m) * N + n;
            float v = __fadd_rn(acc[i][j], bv);
            if constexpr (EPI == 2) {
                float s = sinf(al * v);
                v = v + s * s / al;
            }
            if constexpr (EPI == 3) Out[o] = __fadd_rn(Out[o], -v);
            else                    Out[o] = v;
        }
    }
}

// ====================================================================
// VQ stage A: approximate scores s = cnorm - 2*dot via fp16 mma.
// Block 128 codes x 64 t; keeps the TWO smallest (score, idx) per
// (b, t) per 128-code tile. M=1024, K=128, N=TLAT fixed.
// ====================================================================
__global__ void __launch_bounds__(256) vq_approx_k(
    const float* __restrict__ CB, const float* __restrict__ ZP,
    const float* __restrict__ cnorm,
    float* __restrict__ ps2, int* __restrict__ pi2)
{
    __shared__ __half Ws[128][24];
    __shared__ __half Xs[16][72];
    __shared__ float rS1[64][32];
    __shared__ float rS2[64][32];
    __shared__ int   rI1[64][32];
    __shared__ int   rI2[64][32];

    const int tid  = threadIdx.x;
    const int lane = tid & 31;
    const int warp = tid >> 5;
    const int wm   = warp >> 1;
    const int wn   = warp & 1;
    const int r    = lane >> 2;
    const int c    = lane & 3;

    const int n0 = blockIdx.x * 64;
    const int m0 = blockIdx.y * 128;
    const int b  = blockIdx.z;

    float acc[2][4][4];
#pragma unroll
    for (int mt = 0; mt < 2; mt++)
#pragma unroll
        for (int nt = 0; nt < 4; nt++)
#pragma unroll
            for (int i = 0; i < 4; i++) acc[mt][nt][i] = 0.f;

    const int w_row = tid >> 1;
    const int w_kb  = (tid & 1) * 8;
    const int x_kr  = tid >> 4;
    const int x_nb  = (tid & 15) * 4;

    for (int k0 = 0; k0 < 128; k0 += 16) {
        {
            const float* wp = CB + (size_t)(m0 + w_row) * 128 + k0 + w_kb;
            float4 v0 = *reinterpret_cast<const float4*>(wp);
            float4 v1 = *reinterpret_cast<const float4*>(wp + 4);
            __half* wr = &Ws[w_row][w_kb];
            wr[0] = __float2half(v0.x); wr[1] = __float2half(v0.y);
            wr[2] = __float2half(v0.z); wr[3] = __float2half(v0.w);
            wr[4] = __float2half(v1.x); wr[5] = __float2half(v1.y);
            wr[6] = __float2half(v1.z); wr[7] = __float2half(v1.w);
        }
        {
            const float* xp = ZP + ((size_t)b * 128 + (k0 + x_kr)) * TLAT;
            float v0 = 0.f, v1 = 0.f, v2 = 0.f, v3 = 0.f;
            int n = n0 + x_nb;
            if (n     < TLAT) v0 = xp[n];
            if (n + 1 < TLAT) v1 = xp[n + 1];
            if (n + 2 < TLAT) v2 = xp[n + 2];
            if (n + 3 < TLAT) v3 = xp[n + 3];
            __half* xr = &Xs[x_kr][x_nb];
            xr[0] = __float2half(v0); xr[1] = __float2half(v1);
            xr[2] = __float2half(v2); xr[3] = __float2half(v3);
        }
        __syncthreads();

        unsigned a[2][4];
#pragma unroll
        for (int mt = 0; mt < 2; mt++) {
            int mrow = wm * 32 + mt * 16;
            a[mt][0] = *reinterpret_cast<const unsigned*>(&Ws[mrow + r    ][2*c    ]);
            a[mt][1] = *reinterpret_cast<const unsigned*>(&Ws[mrow + r + 8][2*c    ]);
            a[mt][2] = *reinterpret_cast<const unsigned*>(&Ws[mrow + r    ][2*c + 8]);
            a[mt][3] = *reinterpret_cast<const unsigned*>(&Ws[mrow + r + 8][2*c + 8]);
        }
        unsigned bf[4][2];
#pragma unroll
        for (int nt = 0; nt < 4; nt++) {
            int ncol = wn * 32 + nt * 8 + r;
            unsigned lo0 = *reinterpret_cast<const unsigned short*>(&Xs[2*c    ][ncol]);
            unsigned hi0 = *reinterpret_cast<const unsigned short*>(&Xs[2*c + 1][ncol]);
            bf[nt][0] = lo0 | (hi0 << 16);
            unsigned lo1 = *reinterpret_cast<const unsigned short*>(&Xs[2*c + 8][ncol]);
            unsigned hi1 = *reinterpret_cast<const unsigned short*>(&Xs[2*c + 9][ncol]);
            bf[nt][1] = lo1 | (hi1 << 16);
        }
#pragma unroll
        for (int mt = 0; mt < 2; mt++)
#pragma unroll
            for (int nt = 0; nt < 4; nt++) {
                asm("mma.sync.aligned.m16n8k16.row.col.f32.f16.f16.f32 "
                    "{%0,%1,%2,%3}, {%4,%5,%6,%7}, {%8,%9}, {%0,%1,%2,%3};"
                    : "+f"(acc[mt][nt][0]), "+f"(acc[mt][nt][1]),
                      "+f"(acc[mt][nt][2]), "+f"(acc[mt][nt][3])
                    : "r"(a[mt][0]), "r"(a[mt][1]),
                      "r"(a[mt][2]), "r"(a[mt][3]),
                      "r"(bf[nt][0]), "r"(bf[nt][1]));
            }
        __syncthreads();
    }

    // epilogue: per-(t) top-2 over this block's 128 codes
    float cn4[2][2];
    int   mv4[2][2];
#pragma unroll
    for (int mt = 0; mt < 2; mt++)
#pragma unroll
        for (int g = 0; g < 2; g++) {
            int m = m0 + wm * 32 + mt * 16 + r + 8 * g;
            mv4[mt][g] = m;
            cn4[mt][g] = cnorm[m];
        }
    const int slot = wm * 8 + r;
#pragma unroll
    for (int nt = 0; nt < 4; nt++)
#pragma unroll
        for (int h = 0; h < 2; h++) {
            float a1 = 3.4e38f, a2 = 3.4e38f; int j1 = 0, j2 = 0;
#pragma unroll
            for (int mt = 0; mt < 2; mt++)
#pragma unroll
                for (int g = 0; g < 2; g++) {
                    float s = fmaf(-2.f, acc[mt][nt][2 * g + h], cn4[mt][g]);
                    int idv = mv4[mt][g];
                    if (s < a1) { a2 = a1; j2 = j1; a1 = s; j1 = idv; }
                    else if (s < a2) { a2 = s; j2 = idv; }
                }
            int tl = wn * 32 + nt * 8 + 2 * c + h;
            rS1[tl][slot] = a1; rI1[tl][slot] = j1;
            rS2[tl][slot] = a2; rI2[tl][slot] = j2;
        }
    __syncthreads();

    if (tid < 64) {
        float a1 = 3.4e38f, a2 = 3.4e38f; int j1 = 0, j2 = 0;
#pragma unroll 4
        for (int sl = 0; sl < 32; sl++) {
            float s = rS1[tid][sl]; int idv = rI1[tid][sl];
            if (s < a1) { a2 = a1; j2 = j1; a1 = s; j1 = idv; }
            else if (s < a2) { a2 = s; j2 = idv; }
            s = rS2[tid][sl]; idv = rI2[tid][sl];
            if (s < a1) { a2 = a1; j2 = j1; a1 = s; j1 = idv; }
            else if (s < a2) { a2 = s; j2 = idv; }
        }
        size_t o = (((size_t)blockIdx.y * 64 + b) * 256 + (n0 + tid)) * 2;
        ps2[o] = a1; ps2[o + 1] = a2;
        pi2[o] = j1; pi2[o + 1] = j2;
    }
}

// ====================================================================
// VQ stage B: verified exact selection + zq_st gather + loss.
// eps covers fp16 conversion error (Cauchy-Schwarz, 4x safety) plus the
// reference's score-quantization slack; if a tile's 2nd slot is within
// eps of the approx min, falls back to a full bit-exact 1024 scan.
// All exact arithmetic uses the same sequential-d fp32 chain as the
// reference (ascending d, fmaf) -> codes bit-exact.
// ====================================================================
__global__ void __launch_bounds__(256) vq_select_k(
    const float* __restrict__ ps2, const int* __restrict__ pi2,
    const float* __restrict__ zp, const float* __restrict__ cb,
    const float* __restrict__ cnorm, const float* __restrict__ cnmax_p,
    int book, int* __restrict__ codes, float* __restrict__ zq,
    float* __restrict__ part)
{
    int i = blockIdx.x * 256 + threadIdx.x;
    float local = 0.f;
    if (i < BATCH * TLAT) {
        int b = i / TLAT, t = i - b * TLAT;
        const float* zcol = zp + (size_t)b * 128 * TLAT + t;

        // zn: strict sequential-d chain (reference bits)
        float zn = 0.f;
        for (int d = 0; d < 128; d++) {
            float v = zcol[(size_t)d * TLAT];
            zn = __fmaf_rn(v, v, zn);
        }
        float eps = 0.015625f * sqrtf(zn * cnmax_p[book]) + zn * 2e-6f;

        float s1v[8], s2v[8]; int i1v[8], i2v[8];
        float gmin = 3.4e38f;
#pragma unroll
        for (int tile = 0; tile < 8; tile++) {
            size_t o = (((size_t)tile * 64 + b) * 256 + t) * 2;
            s1v[tile] = ps2[o];     i1v[tile] = pi2[o];
            s2v[tile] = ps2[o + 1]; i2v[tile] = pi2[o + 1];
            gmin = fminf(gmin, s1v[tile]);
        }
        float thr = gmin + eps;
        bool full = false;
#pragma unroll
        for (int tile = 0; tile < 8; tile++)
            if (s2v[tile] <= thr) full = true;

        float best = 3.4e38f; int bi = 0;
        if (full) {
            for (int cidx = 0; cidx < NCODE; cidx++) {
                const float* crow = cb + (size_t)cidx * 128;
                float dot = 0.f;
                for (int d = 0; d < 128; d++)
                    dot = __fmaf_rn(crow[d], zcol[(size_t)d * TLAT], dot);
                float s = __fadd_rn(__fmaf_rn(-2.f, dot, zn), cnorm[cidx]);
                if (s < best) { best = s; bi = cidx; }
            }
        } else {
#pragma unroll
            for (int tile = 0; tile < 8; tile++) {
#pragma unroll
                for (int sl = 0; sl < 2; sl++) {
                    float sa = (sl == 0) ? s1v[tile] : s2v[tile];
                    if (sa > thr) continue;
                    int cidx = (sl == 0) ? i1v[tile] : i2v[tile];
                    const float* crow = cb + (size_t)cidx * 128;
                    float dot = 0.f;
                    for (int d = 0; d < 128; d++)
                        dot = __fmaf_rn(crow[d], zcol[(size_t)d * TLAT], dot);
                    float s = __fadd_rn(__fmaf_rn(-2.f, dot, zn), cnorm[cidx]);
                    if (s < best || (s == best && cidx < bi)) { best = s; bi = cidx; }
                }
            }
        }
        codes[((size_t)b * NBOOK + book) * TLAT + t] = bi;

        // zq_st gather + loss (reference rounding)
        const float* row = cb + (size_t)bi * 128;
        for (int d = 0; d < 128; d++) {
            float zqv = row[d];
            size_t o = ((size_t)b * 128 + d) * TLAT + t;
            float zpv = zcol[(size_t)d * TLAT];
            float diff = __fadd_rn(zqv, -zpv);
            zq[o] = __fadd_rn(zpv, diff);
            local = __fmaf_rn(diff, diff, local);
        }
    }
    __shared__ float red[256];
    red[threadIdx.x] = local;
    __syncthreads();
    for (int s = 128; s > 0; s >>= 1) {
        if (threadIdx.x < s) red[threadIdx.x] += red[threadIdx.x + s];
        __syncthreads();
    }
    if (threadIdx.x == 0) part[book * 63 + blockIdx.x] = red[0];
}

// ====================================================================
// FP16 tensor-core GEMM for decoder D0..D2 (audio path only).
// ====================================================================
__global__ void __launch_bounds__(256, 2) dec_mma_k(
    const float* __restrict__ W, const float* __restrict__ X,
    float* __restrict__ Out, int M, int K, int N)
{
    __shared__ __half Ws[128][24];
    __shared__ __half Xs[16][72];
    const int tid  = threadIdx.x;
    const int lane = tid & 31;
    const int warp = tid >> 5;
    const int wm   = warp >> 1;
    const int wn   = warp & 1;
    const int r    = lane >> 2;
    const int c    = lane & 3;

    const int n0 = blockIdx.x * 64;
    const int m0 = blockIdx.y * 128;
    const int b  = blockIdx.z;

    float acc[2][4][4];
#pragma unroll
    for (int mt = 0; mt < 2; mt++)
#pragma unroll
        for (int nt = 0; nt < 4; nt++)
#pragma unroll
            for (int i = 0; i < 4; i++) acc[mt][nt][i] = 0.f;

    const int w_row = tid >> 1;
    const int w_kb  = (tid & 1) * 8;
    const int x_kr  = tid >> 4;
    const int x_nb  = (tid & 15) * 4;

    for (int k0 = 0; k0 < K; k0 += 16) {
        {
            const float* wp = W + (size_t)(m0 + w_row) * K + k0 + w_kb;
            float4 v0 = *reinterpret_cast<const float4*>(wp);
            float4 v1 = *reinterpret_cast<const float4*>(wp + 4);
            __half* wr = &Ws[w_row][w_kb];
            wr[0] = __float2half(v0.x); wr[1] = __float2half(v0.y);
            wr[2] = __float2half(v0.z); wr[3] = __float2half(v0.w);
            wr[4] = __float2half(v1.x); wr[5] = __float2half(v1.y);
            wr[6] = __float2half(v1.z); wr[7] = __float2half(v1.w);
        }
        {
            const float* xp = X + ((size_t)b * K + (k0 + x_kr)) * N;
            float v0 = 0.f, v1 = 0.f, v2 = 0.f, v3 = 0.f;
            int n = n0 + x_nb;
            if (n     < N) v0 = xp[n];
            if (n + 1 < N) v1 = xp[n + 1];
            if (n + 2 < N) v2 = xp[n + 2];
            if (n + 3 < N) v3 = xp[n + 3];
            __half* xr = &Xs[x_kr][x_nb];
            xr[0] = __float2half(v0); xr[1] = __float2half(v1);
            xr[2] = __float2half(v2); xr[3] = __float2half(v3);
        }
        __syncthreads();

        unsigned a[2][4];
#pragma unroll
        for (int mt = 0; mt < 2; mt++) {
            int mrow = wm * 32 + mt * 16;
            a[mt][0] = *reinterpret_cast<const unsigned*>(&Ws[mrow + r    ][2*c    ]);
            a[mt][1] = *reinterpret_cast<const unsigned*>(&Ws[mrow + r + 8][2*c    ]);
            a[mt][2] = *reinterpret_cast<const unsigned*>(&Ws[mrow + r    ][2*c + 8]);
            a[mt][3] = *reinterpret_cast<const unsigned*>(&Ws[mrow + r + 8][2*c + 8]);
        }
        unsigned bf[4][2];
#pragma unroll
        for (int nt = 0; nt < 4; nt++) {
            int ncol = wn * 32 + nt * 8 + r;
            unsigned lo0 = *reinterpret_cast<const unsigned short*>(&Xs[2*c    ][ncol]);
            unsigned hi0 = *reinterpret_cast<const unsigned short*>(&Xs[2*c + 1][ncol]);
            bf[nt][0] = lo0 | (hi0 << 16);
            unsigned lo1 = *reinterpret_cast<const unsigned short*>(&Xs[2*c + 8][ncol]);
            unsigned hi1 = *reinterpret_cast<const unsigned short*>(&Xs[2*c + 9][ncol]);
            bf[nt][1] = lo1 | (hi1 << 16);
        }
#pragma unroll
        for (int mt = 0; mt < 2; mt++)
#pragma unroll
            for (int nt = 0; nt < 4; nt++) {
                asm("mma.sync.aligned.m16n8k16.row.col.f32.f16.f16.f32 "
                    "{%0,%1,%2,%3}, {%4,%5,%6,%7}, {%8,%9}, {%0,%1,%2,%3};"
                    : "+f"(acc[mt][nt][0]), "+f"(acc[mt][nt][1]),
                      "+f"(acc[mt][nt][2]), "+f"(acc[mt][nt][3])
                    : "r"(a[mt][0]), "r"(a[mt][1]),
                      "r"(a[mt][2]), "r"(a[mt][3]),
                      "r"(bf[nt][0]), "r"(bf[nt][1]));
            }
        __syncthreads();
    }

#pragma unroll
    for (int mt = 0; mt < 2; mt++) {
#pragma unroll
        for (int nt = 0; nt < 4; nt++) {
            int m = m0 + wm * 32 + mt * 16 + r;
            int n = n0 + wn * 32 + nt * 8 + 2 * c;
            float* op = Out + ((size_t)b * M + m) * N;
            if (n < N)     op[n]     = acc[mt][nt][0];
            if (n + 1 < N) op[n + 1] = acc[mt][nt][1];
            op += (size_t)8 * N;
            if (n < N)     op[n]     = acc[mt][nt][2];
            if (n + 1 < N) op[n + 1] = acc[mt][nt][3];
        }
    }
}

// transposed-conv gather (D0..D2)
__global__ void __launch_bounds__(256) convt_gather_k(
    const float* __restrict__ Y, const float* __restrict__ bias,
    const float* __restrict__ alpha, float* __restrict__ out,
    int Cout, int KK, int SS, int PP, int Lin, int Lout)
{
    size_t total = (size_t)BATCH * Cout * Lout;
    size_t i = (size_t)blockIdx.x * 256 + threadIdx.x;
    if (i >= total) return;
    int t  = (int)(i % Lout);
    int co = (int)((i / Lout) % Cout);
    int b  = (int)(i / ((size_t)Lout * Cout));
    int tp = t + PP;
    int q = tp / SS, r = tp - q * SS;
    size_t M = (size_t)Cout * KK;
    float v = bias[co];
    if (q < Lin)  v += Y[((size_t)b * M + (size_t)co * KK + r)      * Lin + q];
    if (q >= 1)   v += Y[((size_t)b * M + (size_t)co * KK + r + SS) * Lin + q - 1];
    float a = alpha[co]; float s = sinf(a * v); v = v + s * s / a;
    out[i] = v;
}

// fused D3: direct transposed conv + tanh
__global__ void __launch_bounds__(256) d3_k(
    const float* __restrict__ X,
    const float* __restrict__ w,
    const float* __restrict__ bias,
    float* __restrict__ out)
{
    __shared__ __align__(16) float ws[64][16];
    const int tid = threadIdx.x;
    for (int i = tid; i < 1024; i += 256) ws[i >> 4][i & 15] = w[i];
    __syncthreads();

    const int b = blockIdx.y;
    const int u = blockIdx.x * 256 + tid;
    const int tbase = u * 16;
    if (tbase >= D3_LOUT) return;

    const float* xb = X + (size_t)b * 64 * D3_LIN;
    const int q0 = 2 * u;

    float acc[16];
#pragma unroll
    for (int i = 0; i < 16; i++) acc[i] = 0.f;

    for (int ci = 0; ci < 64; ci++) {
        const float* xr = xb + (size_t)ci * D3_LIN;
        float xA = (q0 - 1 >= 0)      ? xr[q0 - 1] : 0.f;
        float xB = (q0     < D3_LIN)  ? xr[q0]     : 0.f;
        float xC = (q0 + 1 < D3_LIN)  ? xr[q0 + 1] : 0.f;
        float xD = (q0 + 2 < D3_LIN)  ? xr[q0 + 2] : 0.f;
        const float4* w4 = reinterpret_cast<const float4*>(&ws[ci][0]);
        float4 w0 = w4[0], w1 = w4[1], w2 = w4[2], w3 = w4[3];
        float wv[16] = {w0.x,w0.y,w0.z,w0.w, w1.x,w1.y,w1.z,w1.w,
                        w2.x,w2.y,w2.z,w2.w, w3.x,w3.y,w3.z,w3.w};
#pragma unroll
        for (int tt = 0; tt < 4; tt++)
            acc[tt] = fmaf(wv[4 + tt], xB, fmaf(wv[12 + tt], xA, acc[tt]));
#pragma unroll
        for (int tt = 4; tt < 12; tt++)
            acc[tt] = fmaf(wv[tt - 4], xC, fmaf(wv[tt + 4], xB, acc[tt]));
#pragma unroll
        for (int tt = 12; tt < 16; tt++)
            acc[tt] = fmaf(wv[tt - 12], xD, fmaf(wv[tt - 4], xC, acc[tt]));
    }
    float b0 = bias[0];
    float* op = out + (size_t)b * D3_LOUT + tbase;
#pragma unroll
    for (int i = 0; i < 16; i++) {
        if (tbase + i < D3_LOUT) op[i] = tanhf(acc[i] + b0);
    }
}

__global__ void transpose_w_k(const float* __restrict__ w, float* __restrict__ wt,
                              int Cin, int Cout, int KK)
{
    int i = blockIdx.x * 256 + threadIdx.x;
    int total = Cin * Cout * KK;
    if (i < total) {
        int j  = i % KK;
        int co = (i / KK) % Cout;
        int ci = i / (KK * Cout);
        wt[((size_t)co * KK + j) * Cin + ci] = w[i];
    }
}

__global__ void cnorm_k(const float* __restrict__ cbs, float* __restrict__ cn)
{
    int i = blockIdx.x * 256 + threadIdx.x;
    if (i < NBOOK * NCODE) {
        const float* r = cbs + (size_t)i * 128;
        float s = 0.f;
        for (int d = 0; d < 128; d++) s = __fmaf_rn(r[d], r[d], s);
        cn[i] = s;
    }
}

__global__ void cnmax_k(const float* __restrict__ cn, float* __restrict__ cm)
{
    __shared__ float red[256];
    int bk = blockIdx.x;
    float m = 0.f;
    for (int i = threadIdx.x; i < NCODE; i += 256)
        m = fmaxf(m, cn[bk * NCODE + i]);
    red[threadIdx.x] = m;
    __syncthreads();
    for (int s = 128; s > 0; s >>= 1) {
        if (threadIdx.x < s) red[threadIdx.x] = fmaxf(red[threadIdx.x], red[threadIdx.x + s]);
        __syncthreads();
    }
    if (threadIdx.x == 0) cm[bk] = red[0];
}

__global__ void sub_inplace_k(float* __restrict__ a, const float* __restrict__ b, int n)
{
    int i = blockIdx.x * 256 + threadIdx.x;
    if (i < n) a[i] = __fadd_rn(a[i], -b[i]);
}

__global__ void pack_k(const int* __restrict__ codes, const float* __restrict__ part,
                       float* __restrict__ out)
{
    int i = blockIdx.x * 256 + threadIdx.x;
    if (i < CODES_SZ) out[X_OUT_SZ + i] = (float)codes[i];
    if (i == 0) {
        float s = 0.f;
        for (int j = 0; j < NBOOK * 63; j++) s += part[j];
        out[X_OUT_SZ + CODES_SZ] = 1.25f * s / (float)(BATCH * TLAT * 128);
    }
}

// ====================================================================
extern "C" void kernel_launch(void* const* d_in, const int* in_sizes, int n_in,
                              void* d_out, int out_size)
{
    const float* audio = (const float*)d_in[0];
    const float* ew[4] = {(const float*)d_in[1], (const float*)d_in[4],
                          (const float*)d_in[7], (const float*)d_in[10]};
    const float* eb[4] = {(const float*)d_in[2], (const float*)d_in[5],
                          (const float*)d_in[8], (const float*)d_in[11]};
    const float* ea[4] = {(const float*)d_in[3], (const float*)d_in[6],
                          (const float*)d_in[9], (const float*)d_in[12]};
    const float* dw[4] = {(const float*)d_in[13], (const float*)d_in[16],
                          (const float*)d_in[19], (const float*)d_in[22]};
    const float* db[4] = {(const float*)d_in[14], (const float*)d_in[17],
                          (const float*)d_in[20], (const float*)d_in[23]};
    const float* da[3] = {(const float*)d_in[15], (const float*)d_in[18],
                          (const float*)d_in[21]};
    const float* pin_w  = (const float*)d_in[24];
    const float* pin_b  = (const float*)d_in[25];
    const float* pout_w = (const float*)d_in[26];
    const float* pout_b = (const float*)d_in[27];
    const float* cbs    = (const float*)d_in[28];
    float* out = (float*)d_out;

    float *bufA, *bufB, *z, *res, *zp, *zq, *wt, *cn, *cmax, *part, *ps2;
    int *codes, *pi2;
    cudaGetSymbolAddress((void**)&bufA,  g_bufA);
    cudaGetSymbolAddress((void**)&bufB,  g_bufB);
    cudaGetSymbolAddress((void**)&z,     g_z);
    cudaGetSymbolAddress((void**)&res,   g_res);
    cudaGetSymbolAddress((void**)&zp,    g_zp);
    cudaGetSymbolAddress((void**)&zq,    g_zq);
    cudaGetSymbolAddress((void**)&wt,    g_wt);
    cudaGetSymbolAddress((void**)&cn,    g_cnorm);
    cudaGetSymbolAddress((void**)&cmax,  g_cnmax);
    cudaGetSymbolAddress((void**)&part,  g_part);
    cudaGetSymbolAddress((void**)&codes, g_codes);
    cudaGetSymbolAddress((void**)&ps2,   g_ps2);
    cudaGetSymbolAddress((void**)&pi2,   g_pi2);

    cnorm_k<<<(NBOOK * NCODE + 255) / 256, 256>>>(cbs, cn);
    cnmax_k<<<NBOOK, 256>>>(cn, cmax);

    // ---------------- encoder (bit-exact fp32 path) ----------------
    gemm_k<1, 2, 16, 8, 4><<<dim3(235, 1, 64), 256>>>(
        ew[0], audio, eb[0], ea[0], bufA, 64, 16, 15000, 120000, 1);
    gemm_big_k<1, 2, 10, 5, 2><<<dim3(24, 1, 64), 256>>>(
        ew[1], bufA, eb[1], nullptr, ea[1], bufB, 128, 640, 2999, 15000, 64);
    gemm_big_k<1, 2, 8, 4, 2><<<dim3(6, 2, 64), 256>>>(
        ew[2], bufB, eb[2], nullptr, ea[2], bufA, 256, 1024, 749, 2999, 128);
    gemm_big_k<1, 2, 6, 3, 1><<<dim3(2, 4, 64), 256>>>(
        ew[3], bufA, eb[3], nullptr, ea[3], z, 512, 1536, 249, 749, 256);

    const int NZ = BATCH * 512 * TLAT;

    // ---------------- residual VQ (codes bit-exact) ----------------
    for (int bk = 0; bk < NBOOK; bk++) {
        const float* cb  = cbs + (size_t)bk * NCODE * 128;
        const float* src = (bk == 0) ? z : res;
        gemm_big_k<0, 1, 1, 1, 0><<<dim3(2, 1, 64), 256>>>(
            pin_w, src, pin_b, nullptr, nullptr, zp, 128, 512, TLAT, 0, 0);
        vq_approx_k<<<dim3(4, 8, 64), 256>>>(cb, zp, cn + bk * NCODE, ps2, pi2);
        vq_select_k<<<63, 256>>>(ps2, pi2, zp, cb, cn + bk * NCODE, cmax, bk,
                                 codes, zq, part);
        if (bk == 0)
            gemm_big_k<0, 4, 1, 1, 0><<<dim3(2, 4, 64), 256>>>(
                pout_w, zq, pout_b, z, nullptr, res, 512, 128, TLAT, 0, 0);
        else
            gemm_big_k<0, 3, 1, 1, 0><<<dim3(2, 4, 64), 256>>>(
                pout_w, zq, pout_b, nullptr, nullptr, res, 512, 128, TLAT, 0, 0);
    }
    sub_inplace_k<<<(NZ + 255) / 256, 256>>>(z, res, NZ);   // z_q

    // ---------------- decoder (FP16 tensor cores) ----------------
    transpose_w_k<<<(512 * 256 * 6 + 255) / 256, 256>>>(dw[0], wt, 512, 256, 6);
    dec_mma_k<<<dim3(4, 12, 64), 256>>>(wt, z, bufB, 1536, 512, 249);
    {
        size_t tot = (size_t)BATCH * 256 * 748;
        convt_gather_k<<<(unsigned)((tot + 255) / 256), 256>>>(
            bufB, db[0], da[0], bufA, 256, 6, 3, 1, 249, 748);
    }
    transpose_w_k<<<(256 * 128 * 8 + 255) / 256, 256>>>(dw[1], wt, 256, 128, 8);
    dec_mma_k<<<dim3(12, 8, 64), 256>>>(wt, bufA, bufB, 1024, 256, 748);
    {
        size_t tot = (size_t)BATCH * 128 * 2992;
        convt_gather_k<<<(unsigned)((tot + 255) / 256), 256>>>(
            bufB, db[1], da[1], bufA, 128, 8, 4, 2, 748, 2992);
    }
    transpose_w_k<<<(128 * 64 * 10 + 255) / 256, 256>>>(dw[2], wt, 128, 64, 10);
    dec_mma_k<<<dim3(47, 5, 64), 256>>>(wt, bufA, bufB, 640, 128, 2992);
    {
        size_t tot = (size_t)BATCH * 64 * 14961;
        convt_gather_k<<<(unsigned)((tot + 255) / 256), 256>>>(
            bufB, db[2], da[2], bufA, 64, 10, 5, 2, 2992, 14961);
    }
    d3_k<<<dim3(30, 64), 256>>>(bufA, dw[3], db[3], out);

    // ---------------- codes + vq_loss tail ----------------
    if (out_size >= FULL_OUT)
        pack_k<<<(CODES_SZ + 255) / 256, 256>>>(codes, part, out);
}

// round 16
// speedup vs baseline: 3.6176x; 3.6176x over previous
#include <cuda_runtime.h>
#include <cuda_fp16.h>
#include <math.h>

// ---------------- problem constants ----------------
#define BATCH 64
#define TLAT  249
#define NCODE 1024
#define NBOOK 8

#define X_OUT_SZ   (64*119688)          // 7660032
#define CODES_SZ   (64*8*249)           // 127488
#define FULL_OUT   (X_OUT_SZ + CODES_SZ + 1)

#define D3_LIN  14961
#define D3_LOUT 119688

// ---------------- scratch (static device globals; no allocs) ----------------
__device__ float g_bufA[61440000];
__device__ float g_bufB[122552320];
__device__ float g_z  [BATCH*512*TLAT];
__device__ float g_res[BATCH*512*TLAT];
__device__ float g_zp [BATCH*128*TLAT];
__device__ float g_zq [BATCH*128*TLAT];
__device__ float g_wt [512*256*6];
__device__ int   g_codes[BATCH*NBOOK*TLAT];
__device__ float g_cnorm[NBOOK*NCODE];
__device__ float g_part[NBOOK*63];
__device__ float g_pscore[8*64*256];
__device__ int   g_pidx  [8*64*256];

// ====================================================================
// BIG GEMM (scalar fp32, bitwise-stable sequential-k chain) — encoder
// + RVQ proj GEMMs. This path must remain bit-exact (argmin ties).
//   EPI 0: store ; 1: +bias ; 2: snake ; 3: Out -= (acc+bias)
//   EPI 4: Out = Z2 - (acc+bias)
// ====================================================================
template<int XMODE, int EPI, int KK, int SS, int PP>
__global__ void __launch_bounds__(256, 2) gemm_big_k(
    const float* __restrict__ A, const float* __restrict__ X,
    const float* __restrict__ bias, const float* __restrict__ Z2,
    const float* __restrict__ alpha,
    float* __restrict__ Out,
    int M, int K, int N, int Lin, int Cin)
{
    __shared__ __align__(16) float As[2][16][128];
    __shared__ __align__(16) float Xs[2][16][128];
    const int tid = threadIdx.x;
    const int n0 = blockIdx.x * 128;
    const int m0 = blockIdx.y * 128;
    const int b  = blockIdx.z;
    const int mi = tid >> 4;
    const int ni = tid & 15;

    const int a_row = tid >> 1;
    const int a_k   = (tid & 1) * 8;
    const int x_row = tid >> 4;
    const int x_col = tid & 15;

    float acc[8][8];
#pragma unroll
    for (int i = 0; i < 8; i++)
#pragma unroll
        for (int j = 0; j < 8; j++) acc[i][j] = 0.f;

    float ar[8], xr[8];

    auto loadA = [&](int k0) {
        const float* ap = A + (size_t)(m0 + a_row) * K + (k0 + a_k);
        float4 v0 = *reinterpret_cast<const float4*>(ap);
        float4 v1 = *reinterpret_cast<const float4*>(ap + 4);
        ar[0]=v0.x; ar[1]=v0.y; ar[2]=v0.z; ar[3]=v0.w;
        ar[4]=v1.x; ar[5]=v1.y; ar[6]=v1.z; ar[7]=v1.w;
    };
    auto loadX = [&](int k0) {
        int kidx = k0 + x_row;
        if constexpr (XMODE == 0) {
            const float* xrow = X + ((size_t)b * K + kidx) * N;
#pragma unroll
            for (int c = 0; c < 8; c++) {
                int n = n0 + x_col + 16 * c;
                xr[c] = (n < N) ? xrow[n] : 0.f;
            }
        } else {
            int ci = kidx / KK;
            int jj = kidx - ci * KK;
            const float* xrow = X + ((size_t)b * Cin + ci) * Lin;
#pragma unroll
            for (int c = 0; c < 8; c++) {
                int n = n0 + x_col + 16 * c;
                int x = n * SS - PP + jj;
                xr[c] = (x >= 0 && x < Lin) ? xrow[x] : 0.f;
            }
        }
    };

    loadA(0);
    loadX(0);
#pragma unroll
    for (int c = 0; c < 8; c++) As[0][a_k + c][a_row] = ar[c];
#pragma unroll
    for (int c = 0; c < 8; c++) Xs[0][x_row][x_col + 16 * c] = xr[c];
    __syncthreads();

    int pb = 0;
    for (int k0 = 0; k0 < K; k0 += 16) {
        const bool more = (k0 + 16 < K);
        if (more) { loadA(k0 + 16); loadX(k0 + 16); }

#pragma unroll
        for (int kk = 0; kk < 16; kk++) {
            const float4* Ap = reinterpret_cast<const float4*>(&As[pb][kk][mi * 8]);
            const float4* Xp = reinterpret_cast<const float4*>(&Xs[pb][kk][ni * 8]);
            float4 a0 = Ap[0], a1 = Ap[1];
            float4 x0 = Xp[0], x1 = Xp[1];
            float av[8] = {a0.x,a0.y,a0.z,a0.w,a1.x,a1.y,a1.z,a1.w};
            float xv[8] = {x0.x,x0.y,x0.z,x0.w,x1.x,x1.y,x1.z,x1.w};
#pragma unroll
            for (int i = 0; i < 8; i++)
#pragma unroll
                for (int j = 0; j < 8; j++)
                    acc[i][j] = fmaf(av[i], xv[j], acc[i][j]);
        }

        if (more) {
            int nb = pb ^ 1;
#pragma unroll
            for (int c = 0; c < 8; c++) As[nb][a_k + c][a_row] = ar[c];
#pragma unroll
            for (int c = 0; c < 8; c++) Xs[nb][x_row][x_col + 16 * c] = xr[c];
            __syncthreads();
            pb = nb;
        }
    }

#pragma unroll
    for (int i = 0; i < 8; i++) {
        int m = m0 + mi * 8 + i;
        float bv = 0.f, al = 1.f;
        if constexpr (EPI != 0) bv = bias[m];
        if constexpr (EPI == 2) al = alpha[m];
#pragma unroll
        for (int j = 0; j < 8; j++) {
            int n = n0 + ni * 8 + j;
            if (n >= N) continue;
            size_t o = ((size_t)b * M + m) * N + n;
            float v = __fadd_rn(acc[i][j], bv);
            if constexpr (EPI == 2) {
                float s = sinf(al * v);
                v = v + s * s / al;
            }
            if constexpr (EPI == 3)      Out[o] = __fadd_rn(Out[o], -v);
            else if constexpr (EPI == 4) Out[o] = __fadd_rn(Z2[o], -v);
            else                         Out[o] = v;
        }
    }
}

// ====================================================================
// Small GEMM (64x64x16, 4x4) — only for E0 (M=64, K=16).
// ====================================================================
template<int XMODE, int EPI, int KK, int SS, int PP>
__global__ void __launch_bounds__(256) gemm_k(
    const float* __restrict__ A, const float* __restrict__ X,
    const float* __restrict__ bias, const float* __restrict__ alpha,
    float* __restrict__ Out,
    int M, int K, int N, int Lin, int Cin)
{
    __shared__ __align__(16) float As[16][64];
    __shared__ __align__(16) float Xs[16][64];
    const int tid = threadIdx.x;
    const int n0 = blockIdx.x * 64;
    const int m0 = blockIdx.y * 64;
    const int b  = blockIdx.z;
    const int mi = tid >> 4, ni = tid & 15;

    float acc[4][4];
#pragma unroll
    for (int i = 0; i < 4; i++)
#pragma unroll
        for (int j = 0; j < 4; j++) acc[i][j] = 0.f;

    const int a_row  = tid >> 2;
    const int a_quad = (tid & 3) * 4;
    const int x_kk   = tid >> 4;
    const int x_j    = (tid & 15) * 4;

    for (int k0 = 0; k0 < K; k0 += 16) {
        float4 av4 = make_float4(0.f, 0.f, 0.f, 0.f);
        if (m0 + a_row < M)
            av4 = *reinterpret_cast<const float4*>(
                      A + (size_t)(m0 + a_row) * K + k0 + a_quad);
        As[a_quad + 0][a_row] = av4.x;
        As[a_quad + 1][a_row] = av4.y;
        As[a_quad + 2][a_row] = av4.z;
        As[a_quad + 3][a_row] = av4.w;

        if constexpr (XMODE == 0) {
            const float* xrow = X + ((size_t)b * K + (k0 + x_kk)) * N;
#pragma unroll
            for (int c = 0; c < 4; c++) {
                int n = n0 + x_j + c;
                Xs[x_kk][x_j + c] = (n < N) ? xrow[n] : 0.f;
            }
        } else {
            int kidx = k0 + x_kk;
            int ci   = kidx / KK;
            int jj   = kidx - ci * KK;
            const float* xrow = X + ((size_t)b * Cin + ci) * Lin;
#pragma unroll
            for (int c = 0; c < 4; c++) {
                int n = n0 + x_j + c;
                int x = n * SS - PP + jj;
                Xs[x_kk][x_j + c] = (x >= 0 && x < Lin) ? xrow[x] : 0.f;
            }
        }
        __syncthreads();

#pragma unroll
        for (int kk = 0; kk < 16; kk++) {
            float4 a4 = *reinterpret_cast<const float4*>(&As[kk][mi * 4]);
            float4 x4 = *reinterpret_cast<const float4*>(&Xs[kk][ni * 4]);
            float av[4] = {a4.x, a4.y, a4.z, a4.w};
            float xv[4] = {x4.x, x4.y, x4.z, x4.w};
#pragma unroll
            for (int i = 0; i < 4; i++)
#pragma unroll
                for (int j = 0; j < 4; j++)
                    acc[i][j] = fmaf(av[i], xv[j], acc[i][j]);
        }
        __syncthreads();
    }

#pragma unroll
    for (int i = 0; i < 4; i++) {
        int m = m0 + mi * 4 + i;
        if (m >= M) continue;
        float bv = 0.f, al = 1.f;
        if constexpr (EPI != 0) bv = bias[m];
        if constexpr (EPI == 2) al = alpha[m];
#pragma unroll
        for (int j = 0; j < 4; j++) {
            int n = n0 + ni * 4 + j;
            if (n >= N) continue;
            size_t o = ((size_t)b * M + m) * N + n;
            float v = __fadd_rn(acc[i][j], bv);
            if constexpr (EPI == 2) {
                float s = sinf(al * v);
                v = v + s * s / al;
            }
            if constexpr (EPI == 3) Out[o] = __fadd_rn(Out[o], -v);
            else                    Out[o] = v;
        }
    }
}

// ====================================================================
// Fused VQ distance GEMM + partial argmin (round-14 proven version).
// Dot chain identical to gemm_big_k; znorm accumulated from Xs tiles
// in strict d-ascending order. Score = fl(fl(zn-2dot)+cnorm), ties ->
// lowest index. One (score, idx) partial per 128-code tile per (b,t).
// ====================================================================
__global__ void __launch_bounds__(256, 2) vq_gemm_argmin_k(
    const float* __restrict__ CB, const float* __restrict__ ZP,
    const float* __restrict__ cnorm,
    float* __restrict__ pscore, int* __restrict__ pidx)
{
    __shared__ __align__(16) float As[2][16][128];
    __shared__ __align__(16) float Xs[2][16][128];
    const int tid = threadIdx.x;
    const int n0 = blockIdx.x * 128;
    const int m0 = blockIdx.y * 128;
    const int b  = blockIdx.z;
    const int mi = tid >> 4;
    const int ni = tid & 15;
    const int a_row = tid >> 1;
    const int a_k   = (tid & 1) * 8;
    const int x_row = tid >> 4;
    const int x_col = tid & 15;
    const int K = 128, N = TLAT;

    float acc[8][8];
#pragma unroll
    for (int i = 0; i < 8; i++)
#pragma unroll
        for (int j = 0; j < 8; j++) acc[i][j] = 0.f;

    float zn = 0.f;
    float ar[8], xr[8];

    auto loadA = [&](int k0) {
        const float* ap = CB + (size_t)(m0 + a_row) * K + (k0 + a_k);
        float4 v0 = *reinterpret_cast<const float4*>(ap);
        float4 v1 = *reinterpret_cast<const float4*>(ap + 4);
        ar[0]=v0.x; ar[1]=v0.y; ar[2]=v0.z; ar[3]=v0.w;
        ar[4]=v1.x; ar[5]=v1.y; ar[6]=v1.z; ar[7]=v1.w;
    };
    auto loadX = [&](int k0) {
        const float* xrow = ZP + ((size_t)b * K + (k0 + x_row)) * N;
#pragma unroll
        for (int c = 0; c < 8; c++) {
            int n = n0 + x_col + 16 * c;
            xr[c] = (n < N) ? xrow[n] : 0.f;
        }
    };

    loadA(0);
    loadX(0);
#pragma unroll
    for (int c = 0; c < 8; c++) As[0][a_k + c][a_row] = ar[c];
#pragma unroll
    for (int c = 0; c < 8; c++) Xs[0][x_row][x_col + 16 * c] = xr[c];
    __syncthreads();

    int pb = 0;
    for (int k0 = 0; k0 < K; k0 += 16) {
        const bool more = (k0 + 16 < K);
        if (more) { loadA(k0 + 16); loadX(k0 + 16); }

#pragma unroll
        for (int kk = 0; kk < 16; kk++) {
            const float4* Ap = reinterpret_cast<const float4*>(&As[pb][kk][mi * 8]);
            const float4* Xp = reinterpret_cast<const float4*>(&Xs[pb][kk][ni * 8]);
            float4 a0 = Ap[0], a1 = Ap[1];
            float4 x0 = Xp[0], x1 = Xp[1];
            float av[8] = {a0.x,a0.y,a0.z,a0.w,a1.x,a1.y,a1.z,a1.w};
            float xv[8] = {x0.x,x0.y,x0.z,x0.w,x1.x,x1.y,x1.z,x1.w};
#pragma unroll
            for (int i = 0; i < 8; i++)
#pragma unroll
                for (int j = 0; j < 8; j++)
                    acc[i][j] = fmaf(av[i], xv[j], acc[i][j]);
        }

        if (tid < 128) {
#pragma unroll
            for (int kk = 0; kk < 16; kk++) {
                float v = Xs[pb][kk][tid];
                zn = __fmaf_rn(v, v, zn);
            }
        }

        if (more) {
            int nb = pb ^ 1;
#pragma unroll
            for (int c = 0; c < 8; c++) As[nb][a_k + c][a_row] = ar[c];
#pragma unroll
            for (int c = 0; c < 8; c++) Xs[nb][x_row][x_col + 16 * c] = xr[c];
            __syncthreads();
            pb = nb;
        }
    }

    __syncthreads();
    float* zns = &Xs[0][0][0];
    float* sS  = &As[0][0][0];
    int*   sI  = reinterpret_cast<int*>(&As[1][0][0]);
    if (tid < 128) zns[tid] = zn;
    __syncthreads();

#pragma unroll
    for (int j = 0; j < 8; j++) {
        int nl = ni * 8 + j;
        float zv = zns[nl];
        float bs = 3.4e38f; int bi = 0;
#pragma unroll
        for (int i = 0; i < 8; i++) {
            int m = m0 + mi * 8 + i;
            float s = __fadd_rn(__fmaf_rn(-2.f, acc[i][j], zv), cnorm[m]);
            if (s < bs) { bs = s; bi = m; }
        }
        sS[mi * 128 + nl] = bs;
        sI[mi * 128 + nl] = bi;
    }
    __syncthreads();

    if (tid < 128) {
        int n = n0 + tid;
        if (n < N) {
            float bs = sS[tid]; int bi = sI[tid];
#pragma unroll
            for (int k = 1; k < 16; k++) {
                float s = sS[k * 128 + tid];
                if (s < bs) { bs = s; bi = sI[k * 128 + tid]; }
            }
            int o = (blockIdx.y * BATCH + b) * 256 + n;
            pscore[o] = bs; pidx[o] = bi;
        }
    }
}

// final 8-tile argmin (ascending tile, strict <) + zq_st gather + loss
__global__ void __launch_bounds__(256) vq_finish_k(
    const float* __restrict__ ps, const int* __restrict__ pi,
    const float* __restrict__ cb, const float* __restrict__ zp,
    int book, int* __restrict__ codes, float* __restrict__ zq,
    float* __restrict__ part)
{
    int i = blockIdx.x * 256 + threadIdx.x;
    float local = 0.f;
    if (i < BATCH * TLAT) {
        int b = i / TLAT, t = i - b * TLAT;
        float bs = ps[(size_t)b * 256 + t];
        int   bi = pi[(size_t)b * 256 + t];
#pragma unroll
        for (int mt = 1; mt < 8; mt++) {
            size_t o = ((size_t)mt * BATCH + b) * 256 + t;
            float s = ps[o];
            if (s < bs) { bs = s; bi = pi[o]; }
        }
        codes[((size_t)b * NBOOK + book) * TLAT + t] = bi;

        const float* row = cb + (size_t)bi * 128;
        for (int d = 0; d < 128; d++) {
            float zqv = row[d];
            size_t o = ((size_t)b * 128 + d) * TLAT + t;
            float zpv = zp[o];
            float diff = __fadd_rn(zqv, -zpv);
            zq[o] = __fadd_rn(zpv, diff);
            local = __fmaf_rn(diff, diff, local);
        }
    }
    __shared__ float red[256];
    red[threadIdx.x] = local;
    __syncthreads();
    for (int s = 128; s > 0; s >>= 1) {
        if (threadIdx.x < s) red[threadIdx.x] += red[threadIdx.x + s];
        __syncthreads();
    }
    if (threadIdx.x == 0) part[book * 63 + blockIdx.x] = red[0];
}

// ====================================================================
// FP16 tensor-core GEMM for decoder D0..D2 (audio path only).
// 128m x 128n block, 8 warps (4m x 2n), warp tile 32m x 64n,
// double-buffered smem (one barrier per 16-k tile), 16 HMMA/tile/warp.
// ====================================================================
__global__ void __launch_bounds__(256, 2) dec_mma_k(
    const float* __restrict__ W, const float* __restrict__ X,
    float* __restrict__ Out, int M, int K, int N)
{
    __shared__ __half Ws[2][128][24];
    __shared__ __half Xs[2][16][136];
    const int tid  = threadIdx.x;
    const int lane = tid & 31;
    const int warp = tid >> 5;
    const int wm   = warp >> 1;
    const int wn   = warp & 1;
    const int r    = lane >> 2;
    const int c    = lane & 3;

    const int n0 = blockIdx.x * 128;
    const int m0 = blockIdx.y * 128;
    const int b  = blockIdx.z;

    float acc[2][8][4];
#pragma unroll
    for (int mt = 0; mt < 2; mt++)
#pragma unroll
        for (int nt = 0; nt < 8; nt++)
#pragma unroll
            for (int i = 0; i < 4; i++) acc[mt][nt][i] = 0.f;

    const int w_row = tid >> 1;
    const int w_kb  = (tid & 1) * 8;
    const int x_kr  = tid >> 4;
    const int x_nb  = (tid & 15) * 8;

    float wv[8], xv[8];
    auto loadW = [&](int k0) {
        const float* wp = W + (size_t)(m0 + w_row) * K + k0 + w_kb;
        float4 v0 = *reinterpret_cast<const float4*>(wp);
        float4 v1 = *reinterpret_cast<const float4*>(wp + 4);
        wv[0]=v0.x; wv[1]=v0.y; wv[2]=v0.z; wv[3]=v0.w;
        wv[4]=v1.x; wv[5]=v1.y; wv[6]=v1.z; wv[7]=v1.w;
    };
    auto loadXg = [&](int k0) {
        const float* xp = X + ((size_t)b * K + (k0 + x_kr)) * N;
#pragma unroll
        for (int q = 0; q < 8; q++) {
            int n = n0 + x_nb + q;
            xv[q] = (n < N) ? xp[n] : 0.f;
        }
    };
    auto stage = [&](int bb) {
        __half* wr = &Ws[bb][w_row][w_kb];
#pragma unroll
        for (int q = 0; q < 8; q++) wr[q] = __float2half(wv[q]);
        __half* xr = &Xs[bb][x_kr][x_nb];
#pragma unroll
        for (int q = 0; q < 8; q++) xr[q] = __float2half(xv[q]);
    };

    loadW(0); loadXg(0); stage(0);
    __syncthreads();

    int pb = 0;
    for (int k0 = 0; k0 < K; k0 += 16) {
        const bool more = (k0 + 16 < K);
        if (more) { loadW(k0 + 16); loadXg(k0 + 16); }

        unsigned a[2][4];
#pragma unroll
        for (int mt = 0; mt < 2; mt++) {
            int mrow = wm * 32 + mt * 16;
            a[mt][0] = *reinterpret_cast<const unsigned*>(&Ws[pb][mrow + r    ][2*c    ]);
            a[mt][1] = *reinterpret_cast<const unsigned*>(&Ws[pb][mrow + r + 8][2*c    ]);
            a[mt][2] = *reinterpret_cast<const unsigned*>(&Ws[pb][mrow + r    ][2*c + 8]);
            a[mt][3] = *reinterpret_cast<const unsigned*>(&Ws[pb][mrow + r + 8][2*c + 8]);
        }
#pragma unroll
        for (int nt = 0; nt < 8; nt++) {
            int ncol = wn * 64 + nt * 8 + r;
            unsigned lo0 = *reinterpret_cast<const unsigned short*>(&Xs[pb][2*c    ][ncol]);
            unsigned hi0 = *reinterpret_cast<const unsigned short*>(&Xs[pb][2*c + 1][ncol]);
            unsigned b0 = lo0 | (hi0 << 16);
            unsigned lo1 = *reinterpret_cast<const unsigned short*>(&Xs[pb][2*c + 8][ncol]);
            unsigned hi1 = *reinterpret_cast<const unsigned short*>(&Xs[pb][2*c + 9][ncol]);
            unsigned b1 = lo1 | (hi1 << 16);
#pragma unroll
            for (int mt = 0; mt < 2; mt++) {
                asm("mma.sync.aligned.m16n8k16.row.col.f32.f16.f16.f32 "
                    "{%0,%1,%2,%3}, {%4,%5,%6,%7}, {%8,%9}, {%0,%1,%2,%3};"
                    : "+f"(acc[mt][nt][0]), "+f"(acc[mt][nt][1]),
                      "+f"(acc[mt][nt][2]), "+f"(acc[mt][nt][3])
                    : "r"(a[mt][0]), "r"(a[mt][1]),
                      "r"(a[mt][2]), "r"(a[mt][3]),
                      "r"(b0), "r"(b1));
            }
        }

        if (more) {
            stage(pb ^ 1);
            __syncthreads();
            pb ^= 1;
        }
    }

#pragma unroll
    for (int mt = 0; mt < 2; mt++) {
#pragma unroll
        for (int nt = 0; nt < 8; nt++) {
            int m = m0 + wm * 32 + mt * 16 + r;
            int n = n0 + wn * 64 + nt * 8 + 2 * c;
            float* op = Out + ((size_t)b * M + m) * N;
            if (n < N)     op[n]     = acc[mt][nt][0];
            if (n + 1 < N) op[n + 1] = acc[mt][nt][1];
            op += (size_t)8 * N;
            if (n < N)     op[n]     = acc[mt][nt][2];
            if (n + 1 < N) op[n + 1] = acc[mt][nt][3];
        }
    }
}

// transposed-conv gather (D0..D2)
__global__ void __launch_bounds__(256) convt_gather_k(
    const float* __restrict__ Y, const float* __restrict__ bias,
    const float* __restrict__ alpha, float* __restrict__ out,
    int Cout, int KK, int SS, int PP, int Lin, int Lout)
{
    size_t total = (size_t)BATCH * Cout * Lout;
    size_t i = (size_t)blockIdx.x * 256 + threadIdx.x;
    if (i >= total) return;
    int t  = (int)(i % Lout);
    int co = (int)((i / Lout) % Cout);
    int b  = (int)(i / ((size_t)Lout * Cout));
    int tp = t + PP;
    int q = tp / SS, r = tp - q * SS;
    size_t M = (size_t)Cout * KK;
    float v = bias[co];
    if (q < Lin)  v += Y[((size_t)b * M + (size_t)co * KK + r)      * Lin + q];
    if (q >= 1)   v += Y[((size_t)b * M + (size_t)co * KK + r + SS) * Lin + q - 1];
    float a = alpha[co]; float s = sinf(a * v); v = v + s * s / a;
    out[i] = v;
}

// fused D3: direct transposed conv + tanh
__global__ void __launch_bounds__(256) d3_k(
    const float* __restrict__ X,
    const float* __restrict__ w,
    const float* __restrict__ bias,
    float* __restrict__ out)
{
    __shared__ __align__(16) float ws[64][16];
    const int tid = threadIdx.x;
    for (int i = tid; i < 1024; i += 256) ws[i >> 4][i & 15] = w[i];
    __syncthreads();

    const int b = blockIdx.y;
    const int u = blockIdx.x * 256 + tid;
    const int tbase = u * 16;
    if (tbase >= D3_LOUT) return;

    const float* xb = X + (size_t)b * 64 * D3_LIN;
    const int q0 = 2 * u;

    float acc[16];
#pragma unroll
    for (int i = 0; i < 16; i++) acc[i] = 0.f;

    for (int ci = 0; ci < 64; ci++) {
        const float* xr = xb + (size_t)ci * D3_LIN;
        float xA = (q0 - 1 >= 0)      ? xr[q0 - 1] : 0.f;
        float xB = (q0     < D3_LIN)  ? xr[q0]     : 0.f;
        float xC = (q0 + 1 < D3_LIN)  ? xr[q0 + 1] : 0.f;
        float xD = (q0 + 2 < D3_LIN)  ? xr[q0 + 2] : 0.f;
        const float4* w4 = reinterpret_cast<const float4*>(&ws[ci][0]);
        float4 w0 = w4[0], w1 = w4[1], w2 = w4[2], w3 = w4[3];
        float wv[16] = {w0.x,w0.y,w0.z,w0.w, w1.x,w1.y,w1.z,w1.w,
                        w2.x,w2.y,w2.z,w2.w, w3.x,w3.y,w3.z,w3.w};
#pragma unroll
        for (int tt = 0; tt < 4; tt++)
            acc[tt] = fmaf(wv[4 + tt], xB, fmaf(wv[12 + tt], xA, acc[tt]));
#pragma unroll
        for (int tt = 4; tt < 12; tt++)
            acc[tt] = fmaf(wv[tt - 4], xC, fmaf(wv[tt + 4], xB, acc[tt]));
#pragma unroll
        for (int tt = 12; tt < 16; tt++)
            acc[tt] = fmaf(wv[tt - 12], xD, fmaf(wv[tt - 4], xC, acc[tt]));
    }
    float b0 = bias[0];
    float* op = out + (size_t)b * D3_LOUT + tbase;
#pragma unroll
    for (int i = 0; i < 16; i++) {
        if (tbase + i < D3_LOUT) op[i] = tanhf(acc[i] + b0);
    }
}

__global__ void transpose_w_k(const float* __restrict__ w, float* __restrict__ wt,
                              int Cin, int Cout, int KK)
{
    int i = blockIdx.x * 256 + threadIdx.x;
    int total = Cin * Cout * KK;
    if (i < total) {
        int j  = i % KK;
        int co = (i / KK) % Cout;
        int ci = i / (KK * Cout);
        wt[((size_t)co * KK + j) * Cin + ci] = w[i];
    }
}

__global__ void cnorm_k(const float* __restrict__ cbs, float* __restrict__ cn)
{
    int i = blockIdx.x * 256 + threadIdx.x;
    if (i < NBOOK * NCODE) {
        const float* r = cbs + (size_t)i * 128;
        float s = 0.f;
        for (int d = 0; d < 128; d++) s = __fmaf_rn(r[d], r[d], s);
        cn[i] = s;
    }
}

__global__ void sub_inplace_k(float* __restrict__ a, const float* __restrict__ b, int n)
{
    int i = blockIdx.x * 256 + threadIdx.x;
    if (i < n) a[i] = __fadd_rn(a[i], -b[i]);
}

__global__ void pack_k(const int* __restrict__ codes, const float* __restrict__ part,
                       float* __restrict__ out)
{
    int i = blockIdx.x * 256 + threadIdx.x;
    if (i < CODES_SZ) out[X_OUT_SZ + i] = (float)codes[i];
    if (i == 0) {
        float s = 0.f;
        for (int j = 0; j < NBOOK * 63; j++) s += part[j];
        out[X_OUT_SZ + CODES_SZ] = 1.25f * s / (float)(BATCH * TLAT * 128);
    }
}

// ====================================================================
extern "C" void kernel_launch(void* const* d_in, const int* in_sizes, int n_in,
                              void* d_out, int out_size)
{
    const float* audio = (const float*)d_in[0];
    const float* ew[4] = {(const float*)d_in[1], (const float*)d_in[4],
                          (const float*)d_in[7], (const float*)d_in[10]};
    const float* eb[4] = {(const float*)d_in[2], (const float*)d_in[5],
                          (const float*)d_in[8], (const float*)d_in[11]};
    const float* ea[4] = {(const float*)d_in[3], (const float*)d_in[6],
                          (const float*)d_in[9], (const float*)d_in[12]};
    const float* dw[4] = {(const float*)d_in[13], (const float*)d_in[16],
                          (const float*)d_in[19], (const float*)d_in[22]};
    const float* db[4] = {(const float*)d_in[14], (const float*)d_in[17],
                          (const float*)d_in[20], (const float*)d_in[23]};
    const float* da[3] = {(const float*)d_in[15], (const float*)d_in[18],
                          (const float*)d_in[21]};
    const float* pin_w  = (const float*)d_in[24];
    const float* pin_b  = (const float*)d_in[25];
    const float* pout_w = (const float*)d_in[26];
    const float* pout_b = (const float*)d_in[27];
    const float* cbs    = (const float*)d_in[28];
    float* out = (float*)d_out;

    float *bufA, *bufB, *z, *res, *zp, *zq, *wt, *cn, *part, *pscore;
    int *codes, *pidx;
    cudaGetSymbolAddress((void**)&bufA,   g_bufA);
    cudaGetSymbolAddress((void**)&bufB,   g_bufB);
    cudaGetSymbolAddress((void**)&z,      g_z);
    cudaGetSymbolAddress((void**)&res,    g_res);
    cudaGetSymbolAddress((void**)&zp,     g_zp);
    cudaGetSymbolAddress((void**)&zq,     g_zq);
    cudaGetSymbolAddress((void**)&wt,     g_wt);
    cudaGetSymbolAddress((void**)&cn,     g_cnorm);
    cudaGetSymbolAddress((void**)&part,   g_part);
    cudaGetSymbolAddress((void**)&codes,  g_codes);
    cudaGetSymbolAddress((void**)&pscore, g_pscore);
    cudaGetSymbolAddress((void**)&pidx,   g_pidx);

    cnorm_k<<<(NBOOK * NCODE + 255) / 256, 256>>>(cbs, cn);

    // ---------------- encoder (bit-exact fp32 path) ----------------
    gemm_k<1, 2, 16, 8, 4><<<dim3(235, 1, 64), 256>>>(
        ew[0], audio, eb[0], ea[0], bufA, 64, 16, 15000, 120000, 1);
    gemm_big_k<1, 2, 10, 5, 2><<<dim3(24, 1, 64), 256>>>(
        ew[1], bufA, eb[1], nullptr, ea[1], bufB, 128, 640, 2999, 15000, 64);
    gemm_big_k<1, 2, 8, 4, 2><<<dim3(6, 2, 64), 256>>>(
        ew[2], bufB, eb[2], nullptr, ea[2], bufA, 256, 1024, 749, 2999, 128);
    gemm_big_k<1, 2, 6, 3, 1><<<dim3(2, 4, 64), 256>>>(
        ew[3], bufA, eb[3], nullptr, ea[3], z, 512, 1536, 249, 749, 256);

    const int NZ = BATCH * 512 * TLAT;

    // ---------------- residual VQ (codes bit-exact; round-14 path) ----
    for (int bk = 0; bk < NBOOK; bk++) {
        const float* cb  = cbs + (size_t)bk * NCODE * 128;
        const float* src = (bk == 0) ? z : res;
        gemm_big_k<0, 1, 1, 1, 0><<<dim3(2, 1, 64), 256>>>(
            pin_w, src, pin_b, nullptr, nullptr, zp, 128, 512, TLAT, 0, 0);
        vq_gemm_argmin_k<<<dim3(2, 8, 64), 256>>>(
            cb, zp, cn + bk * NCODE, pscore, pidx);
        vq_finish_k<<<63, 256>>>(pscore, pidx, cb, zp, bk, codes, zq, part);
        if (bk == 0)
            gemm_big_k<0, 4, 1, 1, 0><<<dim3(2, 4, 64), 256>>>(
                pout_w, zq, pout_b, z, nullptr, res, 512, 128, TLAT, 0, 0);
        else
            gemm_big_k<0, 3, 1, 1, 0><<<dim3(2, 4, 64), 256>>>(
                pout_w, zq, pout_b, nullptr, nullptr, res, 512, 128, TLAT, 0, 0);
    }
    sub_inplace_k<<<(NZ + 255) / 256, 256>>>(z, res, NZ);   // z_q

    // ---------------- decoder (FP16 tensor cores) ----------------
    transpose_w_k<<<(512 * 256 * 6 + 255) / 256, 256>>>(dw[0], wt, 512, 256, 6);
    dec_mma_k<<<dim3(2, 12, 64), 256>>>(wt, z, bufB, 1536, 512, 249);
    {
        size_t tot = (size_t)BATCH * 256 * 748;
        convt_gather_k<<<(unsigned)((tot + 255) / 256), 256>>>(
            bufB, db[0], da[0], bufA, 256, 6, 3, 1, 249, 748);
    }
    transpose_w_k<<<(256 * 128 * 8 + 255) / 256, 256>>>(dw[1], wt, 256, 128, 8);
    dec_mma_k<<<dim3(6, 8, 64), 256>>>(wt, bufA, bufB, 1024, 256, 748);
    {
        size_t tot = (size_t)BATCH * 128 * 2992;
        convt_gather_k<<<(unsigned)((tot + 255) / 256), 256>>>(
            bufB, db[1], da[1], bufA, 128, 8, 4, 2, 748, 2992);
    }
    transpose_w_k<<<(128 * 64 * 10 + 255) / 256, 256>>>(dw[2], wt, 128, 64, 10);
    dec_mma_k<<<dim3(24, 5, 64), 256>>>(wt, bufA, bufB, 640, 128, 2992);
    {
        size_t tot = (size_t)BATCH * 64 * 14961;
        convt_gather_k<<<(unsigned)((tot + 255) / 256), 256>>>(
            bufB, db[2], da[2], bufA, 64, 10, 5, 2, 2992, 14961);
    }
    d3_k<<<dim3(30, 64), 256>>>(bufA, dw[3], db[3], out);

    // ---------------- codes + vq_loss tail ----------------
    if (out_size >= FULL_OUT)
        pack_k<<<(CODES_SZ + 255) / 256, 256>>>(codes, part, out);
}

// round 17
// speedup vs baseline: 3.6688x; 1.0142x over previous
#include <cuda_runtime.h>
#include <cuda_fp16.h>
#include <math.h>

// ---------------- problem constants ----------------
#define BATCH 64
#define TLAT  249
#define NCODE 1024
#define NBOOK 8

#define X_OUT_SZ   (64*119688)          // 7660032
#define CODES_SZ   (64*8*249)           // 127488
#define FULL_OUT   (X_OUT_SZ + CODES_SZ + 1)

#define D3_LIN  14961
#define D3_LOUT 119688

// ---------------- scratch (static device globals; no allocs) ----------------
__device__ float g_bufA[61440000];
__device__ float g_bufB[122552320];
__device__ float g_z  [BATCH*512*TLAT];
__device__ float g_res[BATCH*512*TLAT];
__device__ float g_zp [BATCH*128*TLAT];
__device__ float g_zq [BATCH*128*TLAT];
__device__ int   g_codes[BATCH*NBOOK*TLAT];
__device__ float g_cnorm[NBOOK*NCODE];
__device__ float g_part[NBOOK*63];
__device__ float g_pscore[8*64*256];
__device__ int   g_pidx  [8*64*256];

// ====================================================================
// BIG GEMM (scalar fp32, bitwise-stable sequential-k chain) — encoder
// + RVQ proj GEMMs. This path must remain bit-exact (argmin ties).
//   EPI 0: store ; 1: +bias ; 2: snake ; 3: Out -= (acc+bias)
//   EPI 4: Out = Z2 - (acc+bias)
//   EPI 5: Out2 = fl(Z2 - fl(Out - (acc+bias)))   (fused res-update + z_q)
// ====================================================================
template<int XMODE, int EPI, int KK, int SS, int PP>
__global__ void __launch_bounds__(256, 2) gemm_big_k(
    const float* __restrict__ A, const float* __restrict__ X,
    const float* __restrict__ bias, const float* __restrict__ Z2,
    const float* __restrict__ alpha,
    float* __restrict__ Out, float* __restrict__ Out2,
    int M, int K, int N, int Lin, int Cin)
{
    __shared__ __align__(16) float As[2][16][128];
    __shared__ __align__(16) float Xs[2][16][128];
    const int tid = threadIdx.x;
    const int n0 = blockIdx.x * 128;
    const int m0 = blockIdx.y * 128;
    const int b  = blockIdx.z;
    const int mi = tid >> 4;
    const int ni = tid & 15;

    const int a_row = tid >> 1;
    const int a_k   = (tid & 1) * 8;
    const int x_row = tid >> 4;
    const int x_col = tid & 15;

    float acc[8][8];
#pragma unroll
    for (int i = 0; i < 8; i++)
#pragma unroll
        for (int j = 0; j < 8; j++) acc[i][j] = 0.f;

    float ar[8], xr[8];

    auto loadA = [&](int k0) {
        const float* ap = A + (size_t)(m0 + a_row) * K + (k0 + a_k);
        float4 v0 = *reinterpret_cast<const float4*>(ap);
        float4 v1 = *reinterpret_cast<const float4*>(ap + 4);
        ar[0]=v0.x; ar[1]=v0.y; ar[2]=v0.z; ar[3]=v0.w;
        ar[4]=v1.x; ar[5]=v1.y; ar[6]=v1.z; ar[7]=v1.w;
    };
    auto loadX = [&](int k0) {
        int kidx = k0 + x_row;
        if constexpr (XMODE == 0) {
            const float* xrow = X + ((size_t)b * K + kidx) * N;
#pragma unroll
            for (int c = 0; c < 8; c++) {
                int n = n0 + x_col + 16 * c;
                xr[c] = (n < N) ? xrow[n] : 0.f;
            }
        } else {
            int ci = kidx / KK;
            int jj = kidx - ci * KK;
            const float* xrow = X + ((size_t)b * Cin + ci) * Lin;
#pragma unroll
            for (int c = 0; c < 8; c++) {
                int n = n0 + x_col + 16 * c;
                int x = n * SS - PP + jj;
                xr[c] = (x >= 0 && x < Lin) ? xrow[x] : 0.f;
            }
        }
    };

    loadA(0);
    loadX(0);
#pragma unroll
    for (int c = 0; c < 8; c++) As[0][a_k + c][a_row] = ar[c];
#pragma unroll
    for (int c = 0; c < 8; c++) Xs[0][x_row][x_col + 16 * c] = xr[c];
    __syncthreads();

    int pb = 0;
    for (int k0 = 0; k0 < K; k0 += 16) {
        const bool more = (k0 + 16 < K);
        if (more) { loadA(k0 + 16); loadX(k0 + 16); }

#pragma unroll
        for (int kk = 0; kk < 16; kk++) {
            const float4* Ap = reinterpret_cast<const float4*>(&As[pb][kk][mi * 8]);
            const float4* Xp = reinterpret_cast<const float4*>(&Xs[pb][kk][ni * 8]);
            float4 a0 = Ap[0], a1 = Ap[1];
            float4 x0 = Xp[0], x1 = Xp[1];
            float av[8] = {a0.x,a0.y,a0.z,a0.w,a1.x,a1.y,a1.z,a1.w};
            float xv[8] = {x0.x,x0.y,x0.z,x0.w,x1.x,x1.y,x1.z,x1.w};
#pragma unroll
            for (int i = 0; i < 8; i++)
#pragma unroll
                for (int j = 0; j < 8; j++)
                    acc[i][j] = fmaf(av[i], xv[j], acc[i][j]);
        }

        if (more) {
            int nb = pb ^ 1;
#pragma unroll
            for (int c = 0; c < 8; c++) As[nb][a_k + c][a_row] = ar[c];
#pragma unroll
            for (int c = 0; c < 8; c++) Xs[nb][x_row][x_col + 16 * c] = xr[c];
            __syncthreads();
            pb = nb;
        }
    }

#pragma unroll
    for (int i = 0; i < 8; i++) {
        int m = m0 + mi * 8 + i;
        float bv = 0.f, al = 1.f;
        if constexpr (EPI != 0) bv = bias[m];
        if constexpr (EPI == 2) al = alpha[m];
#pragma unroll
        for (int j = 0; j < 8; j++) {
            int n = n0 + ni * 8 + j;
            if (n >= N) continue;
            size_t o = ((size_t)b * M + m) * N + n;
            float v = __fadd_rn(acc[i][j], bv);
            if constexpr (EPI == 2) {
                float s = sinf(al * v);
                v = v + s * s / al;
            }
            if constexpr (EPI == 3)      Out[o] = __fadd_rn(Out[o], -v);
            else if constexpr (EPI == 4) Out[o] = __fadd_rn(Z2[o], -v);
            else if constexpr (EPI == 5) {
                float rn = __fadd_rn(Out[o], -v);      // res_new = fl(res - v)
                Out2[o] = __fadd_rn(Z2[o], -rn);       // z_q = fl(z - res_new)
            }
            else                         Out[o] = v;
        }
    }
}

// ====================================================================
// E0 direct conv (Cin=1, Cout=64, k=16, s=8, p=4) + snake.
// Chain identical to the old GEMM path: j ascending fmaf, fadd_rn bias,
// same snake expression -> bit-exact output.
// Block: 64 co x 128 n for one b. Thread: 8 co x 4 strided n.
// xs is swizzle-padded (phys = i + i/32) for conflict-free reads.
// ====================================================================
__global__ void __launch_bounds__(256) e0_k(
    const float* __restrict__ x,     // [B][120000]
    const float* __restrict__ w,     // [64][1][16]
    const float* __restrict__ bias,  // [64]
    const float* __restrict__ alpha, // [64]
    float* __restrict__ out)         // [B][64][15000]
{
    __shared__ float xs[1065];       // 1032 + pad
    __shared__ float ws[64][16];
    const int tid = threadIdx.x;
    const int b   = blockIdx.y;
    const int n0  = blockIdx.x * 128;

    for (int i = tid; i < 1024; i += 256) ws[i >> 4][i & 15] = w[i];
    const float* xb = x + (size_t)b * 120000;
    const int base = 8 * n0 - 4;
    for (int i = tid; i < 1032; i += 256) {
        int xi = base + i;
        xs[i + (i >> 5)] = (xi >= 0 && xi < 120000) ? xb[xi] : 0.f;
    }
    __syncthreads();

    const int nl = tid & 31;    // n = n0 + nl + 32q
    const int cg = tid >> 5;    // co base = cg*8

    float acc[8][4];
#pragma unroll
    for (int cc = 0; cc < 8; cc++)
#pragma unroll
        for (int q = 0; q < 4; q++) acc[cc][q] = 0.f;

#pragma unroll
    for (int j = 0; j < 16; j++) {
        float xv[4];
#pragma unroll
        for (int q = 0; q < 4; q++) {
            int pos = 8 * (nl + 32 * q) + j;           // relative to base
            xv[q] = xs[pos + (pos >> 5)];
        }
#pragma unroll
        for (int cc = 0; cc < 8; cc++) {
            float wv = ws[cg * 8 + cc][j];
#pragma unroll
            for (int q = 0; q < 4; q++)
                acc[cc][q] = fmaf(wv, xv[q], acc[cc][q]);
        }
    }

#pragma unroll
    for (int cc = 0; cc < 8; cc++) {
        int co = cg * 8 + cc;
        float bv = bias[co], al = alpha[co];
        float* op = out + ((size_t)b * 64 + co) * 15000;
#pragma unroll
        for (int q = 0; q < 4; q++) {
            int n = n0 + nl + 32 * q;
            if (n < 15000) {
                float v = __fadd_rn(acc[cc][q], bv);
                float s = sinf(al * v);
                v = v + s * s / al;
                op[n] = v;
            }
        }
    }
}

// ====================================================================
// Fused VQ distance GEMM + partial argmin (round-14 proven version).
// ====================================================================
__global__ void __launch_bounds__(256, 2) vq_gemm_argmin_k(
    const float* __restrict__ CB, const float* __restrict__ ZP,
    const float* __restrict__ cnorm,
    float* __restrict__ pscore, int* __restrict__ pidx)
{
    __shared__ __align__(16) float As[2][16][128];
    __shared__ __align__(16) float Xs[2][16][128];
    const int tid = threadIdx.x;
    const int n0 = blockIdx.x * 128;
    const int m0 = blockIdx.y * 128;
    const int b  = blockIdx.z;
    const int mi = tid >> 4;
    const int ni = tid & 15;
    const int a_row = tid >> 1;
    const int a_k   = (tid & 1) * 8;
    const int x_row = tid >> 4;
    const int x_col = tid & 15;
    const int K = 128, N = TLAT;

    float acc[8][8];
#pragma unroll
    for (int i = 0; i < 8; i++)
#pragma unroll
        for (int j = 0; j < 8; j++) acc[i][j] = 0.f;

    float zn = 0.f;
    float ar[8], xr[8];

    auto loadA = [&](int k0) {
        const float* ap = CB + (size_t)(m0 + a_row) * K + (k0 + a_k);
        float4 v0 = *reinterpret_cast<const float4*>(ap);
        float4 v1 = *reinterpret_cast<const float4*>(ap + 4);
        ar[0]=v0.x; ar[1]=v0.y; ar[2]=v0.z; ar[3]=v0.w;
        ar[4]=v1.x; ar[5]=v1.y; ar[6]=v1.z; ar[7]=v1.w;
    };
    auto loadX = [&](int k0) {
        const float* xrow = ZP + ((size_t)b * K + (k0 + x_row)) * N;
#pragma unroll
        for (int c = 0; c < 8; c++) {
            int n = n0 + x_col + 16 * c;
            xr[c] = (n < N) ? xrow[n] : 0.f;
        }
    };

    loadA(0);
    loadX(0);
#pragma unroll
    for (int c = 0; c < 8; c++) As[0][a_k + c][a_row] = ar[c];
#pragma unroll
    for (int c = 0; c < 8; c++) Xs[0][x_row][x_col + 16 * c] = xr[c];
    __syncthreads();

    int pb = 0;
    for (int k0 = 0; k0 < K; k0 += 16) {
        const bool more = (k0 + 16 < K);
        if (more) { loadA(k0 + 16); loadX(k0 + 16); }

#pragma unroll
        for (int kk = 0; kk < 16; kk++) {
            const float4* Ap = reinterpret_cast<const float4*>(&As[pb][kk][mi * 8]);
            const float4* Xp = reinterpret_cast<const float4*>(&Xs[pb][kk][ni * 8]);
            float4 a0 = Ap[0], a1 = Ap[1];
            float4 x0 = Xp[0], x1 = Xp[1];
            float av[8] = {a0.x,a0.y,a0.z,a0.w,a1.x,a1.y,a1.z,a1.w};
            float xv[8] = {x0.x,x0.y,x0.z,x0.w,x1.x,x1.y,x1.z,x1.w};
#pragma unroll
            for (int i = 0; i < 8; i++)
#pragma unroll
                for (int j = 0; j < 8; j++)
                    acc[i][j] = fmaf(av[i], xv[j], acc[i][j]);
        }

        if (tid < 128) {
#pragma unroll
            for (int kk = 0; kk < 16; kk++) {
                float v = Xs[pb][kk][tid];
                zn = __fmaf_rn(v, v, zn);
            }
        }

        if (more) {
            int nb = pb ^ 1;
#pragma unroll
            for (int c = 0; c < 8; c++) As[nb][a_k + c][a_row] = ar[c];
#pragma unroll
            for (int c = 0; c < 8; c++) Xs[nb][x_row][x_col + 16 * c] = xr[c];
            __syncthreads();
            pb = nb;
        }
    }

    __syncthreads();
    float* zns = &Xs[0][0][0];
    float* sS  = &As[0][0][0];
    int*   sI  = reinterpret_cast<int*>(&As[1][0][0]);
    if (tid < 128) zns[tid] = zn;
    __syncthreads();

#pragma unroll
    for (int j = 0; j < 8; j++) {
        int nl = ni * 8 + j;
        float zv = zns[nl];
        float bs = 3.4e38f; int bi = 0;
#pragma unroll
        for (int i = 0; i < 8; i++) {
            int m = m0 + mi * 8 + i;
            float s = __fadd_rn(__fmaf_rn(-2.f, acc[i][j], zv), cnorm[m]);
            if (s < bs) { bs = s; bi = m; }
        }
        sS[mi * 128 + nl] = bs;
        sI[mi * 128 + nl] = bi;
    }
    __syncthreads();

    if (tid < 128) {
        int n = n0 + tid;
        if (n < N) {
            float bs = sS[tid]; int bi = sI[tid];
#pragma unroll
            for (int k = 1; k < 16; k++) {
                float s = sS[k * 128 + tid];
                if (s < bs) { bs = s; bi = sI[k * 128 + tid]; }
            }
            int o = (blockIdx.y * BATCH + b) * 256 + n;
            pscore[o] = bs; pidx[o] = bi;
        }
    }
}

// final 8-tile argmin (ascending tile, strict <) + zq_st gather + loss
__global__ void __launch_bounds__(256) vq_finish_k(
    const float* __restrict__ ps, const int* __restrict__ pi,
    const float* __restrict__ cb, const float* __restrict__ zp,
    int book, int* __restrict__ codes, float* __restrict__ zq,
    float* __restrict__ part)
{
    int i = blockIdx.x * 256 + threadIdx.x;
    float local = 0.f;
    if (i < BATCH * TLAT) {
        int b = i / TLAT, t = i - b * TLAT;
        float bs = ps[(size_t)b * 256 + t];
        int   bi = pi[(size_t)b * 256 + t];
#pragma unroll
        for (int mt = 1; mt < 8; mt++) {
            size_t o = ((size_t)mt * BATCH + b) * 256 + t;
            float s = ps[o];
            if (s < bs) { bs = s; bi = pi[o]; }
        }
        codes[((size_t)b * NBOOK + book) * TLAT + t] = bi;

        const float* row = cb + (size_t)bi * 128;
        for (int d = 0; d < 128; d++) {
            float zqv = row[d];
            size_t o = ((size_t)b * 128 + d) * TLAT + t;
            float zpv = zp[o];
            float diff = __fadd_rn(zqv, -zpv);
            zq[o] = __fadd_rn(zpv, diff);
            local = __fmaf_rn(diff, diff, local);
        }
    }
    __shared__ float red[256];
    red[threadIdx.x] = local;
    __syncthreads();
    for (int s = 128; s > 0; s >>= 1) {
        if (threadIdx.x < s) red[threadIdx.x] += red[threadIdx.x + s];
        __syncthreads();
    }
    if (threadIdx.x == 0) part[book * 63 + blockIdx.x] = red[0];
}

// ====================================================================
// FP16 tensor-core GEMM for decoder D0..D2 (audio path only).
// 128m x 128n block, warp tile 32m x 64n, double-buffered smem.
// WDIR=1: W read directly from dw layout (wt[m][k] = dw[k*M + m]).
// ====================================================================
template<int WDIR>
__global__ void __launch_bounds__(256, 2) dec_mma_k(
    const float* __restrict__ W, const float* __restrict__ X,
    float* __restrict__ Out, int M, int K, int N)
{
    __shared__ __half Ws[2][128][24];
    __shared__ __half Xs[2][16][136];
    const int tid  = threadIdx.x;
    const int lane = tid & 31;
    const int warp = tid >> 5;
    const int wm   = warp >> 1;
    const int wn   = warp & 1;
    const int r    = lane >> 2;
    const int c    = lane & 3;

    const int n0 = blockIdx.x * 128;
    const int m0 = blockIdx.y * 128;
    const int b  = blockIdx.z;

    float acc[2][8][4];
#pragma unroll
    for (int mt = 0; mt < 2; mt++)
#pragma unroll
        for (int nt = 0; nt < 8; nt++)
#pragma unroll
            for (int i = 0; i < 4; i++) acc[mt][nt][i] = 0.f;

    const int w_row = tid >> 1;
    const int w_kb  = (tid & 1) * 8;
    const int x_kr  = tid >> 4;
    const int x_nb  = (tid & 15) * 8;

    float wv[8], xv[8];
    auto loadW = [&](int k0) {
        if constexpr (WDIR == 0) {
            const float* wp = W + (size_t)(m0 + w_row) * K + k0 + w_kb;
            float4 v0 = *reinterpret_cast<const float4*>(wp);
            float4 v1 = *reinterpret_cast<const float4*>(wp + 4);
            wv[0]=v0.x; wv[1]=v0.y; wv[2]=v0.z; wv[3]=v0.w;
            wv[4]=v1.x; wv[5]=v1.y; wv[6]=v1.z; wv[7]=v1.w;
        } else {
            const float* wp = W + (size_t)(k0 + w_kb) * M + (m0 + w_row);
#pragma unroll
            for (int q = 0; q < 8; q++) wv[q] = wp[(size_t)q * M];
        }
    };
    auto loadXg = [&](int k0) {
        const float* xp = X + ((size_t)b * K + (k0 + x_kr)) * N;
#pragma unroll
        for (int q = 0; q < 8; q++) {
            int n = n0 + x_nb + q;
            xv[q] = (n < N) ? xp[n] : 0.f;
        }
    };
    auto stage = [&](int bb) {
        __half* wr = &Ws[bb][w_row][w_kb];
#pragma unroll
        for (int q = 0; q < 8; q++) wr[q] = __float2half(wv[q]);
        __half* xr = &Xs[bb][x_kr][x_nb];
#pragma unroll
        for (int q = 0; q < 8; q++) xr[q] = __float2half(xv[q]);
    };

    loadW(0); loadXg(0); stage(0);
    __syncthreads();

    int pb = 0;
    for (int k0 = 0; k0 < K; k0 += 16) {
        const bool more = (k0 + 16 < K);
        if (more) { loadW(k0 + 16); loadXg(k0 + 16); }

        unsigned a[2][4];
#pragma unroll
        for (int mt = 0; mt < 2; mt++) {
            int mrow = wm * 32 + mt * 16;
            a[mt][0] = *reinterpret_cast<const unsigned*>(&Ws[pb][mrow + r    ][2*c    ]);
            a[mt][1] = *reinterpret_cast<const unsigned*>(&Ws[pb][mrow + r + 8][2*c    ]);
            a[mt][2] = *reinterpret_cast<const unsigned*>(&Ws[pb][mrow + r    ][2*c + 8]);
            a[mt][3] = *reinterpret_cast<const unsigned*>(&Ws[pb][mrow + r + 8][2*c + 8]);
        }
#pragma unroll
        for (int nt = 0; nt < 8; nt++) {
            int ncol = wn * 64 + nt * 8 + r;
            unsigned lo0 = *reinterpret_cast<const unsigned short*>(&Xs[pb][2*c    ][ncol]);
            unsigned hi0 = *reinterpret_cast<const unsigned short*>(&Xs[pb][2*c + 1][ncol]);
            unsigned b0 = lo0 | (hi0 << 16);
            unsigned lo1 = *reinterpret_cast<const unsigned short*>(&Xs[pb][2*c + 8][ncol]);
            unsigned hi1 = *reinterpret_cast<const unsigned short*>(&Xs[pb][2*c + 9][ncol]);
            unsigned b1 = lo1 | (hi1 << 16);
#pragma unroll
            for (int mt = 0; mt < 2; mt++) {
                asm("mma.sync.aligned.m16n8k16.row.col.f32.f16.f16.f32 "
                    "{%0,%1,%2,%3}, {%4,%5,%6,%7}, {%8,%9}, {%0,%1,%2,%3};"
                    : "+f"(acc[mt][nt][0]), "+f"(acc[mt][nt][1]),
                      "+f"(acc[mt][nt][2]), "+f"(acc[mt][nt][3])
                    : "r"(a[mt][0]), "r"(a[mt][1]),
                      "r"(a[mt][2]), "r"(a[mt][3]),
                      "r"(b0), "r"(b1));
            }
        }

        if (more) {
            stage(pb ^ 1);
            __syncthreads();
            pb ^= 1;
        }
    }

#pragma unroll
    for (int mt = 0; mt < 2; mt++) {
#pragma unroll
        for (int nt = 0; nt < 8; nt++) {
            int m = m0 + wm * 32 + mt * 16 + r;
            int n = n0 + wn * 64 + nt * 8 + 2 * c;
            float* op = Out + ((size_t)b * M + m) * N;
            if (n < N)     op[n]     = acc[mt][nt][0];
            if (n + 1 < N) op[n + 1] = acc[mt][nt][1];
            op += (size_t)8 * N;
            if (n < N)     op[n]     = acc[mt][nt][2];
            if (n + 1 < N) op[n + 1] = acc[mt][nt][3];
        }
    }
}

// transposed-conv gather (D0..D2)
__global__ void __launch_bounds__(256) convt_gather_k(
    const float* __restrict__ Y, const float* __restrict__ bias,
    const float* __restrict__ alpha, float* __restrict__ out,
    int Cout, int KK, int SS, int PP, int Lin, int Lout)
{
    size_t total = (size_t)BATCH * Cout * Lout;
    size_t i = (size_t)blockIdx.x * 256 + threadIdx.x;
    if (i >= total) return;
    int t  = (int)(i % Lout);
    int co = (int)((i / Lout) % Cout);
    int b  = (int)(i / ((size_t)Lout * Cout));
    int tp = t + PP;
    int q = tp / SS, r = tp - q * SS;
    size_t M = (size_t)Cout * KK;
    float v = bias[co];
    if (q < Lin)  v += Y[((size_t)b * M + (size_t)co * KK + r)      * Lin + q];
    if (q >= 1)   v += Y[((size_t)b * M + (size_t)co * KK + r + SS) * Lin + q - 1];
    float a = alpha[co]; float s = sinf(a * v); v = v + s * s / a;
    out[i] = v;
}

// fused D3: direct transposed conv + tanh
__global__ void __launch_bounds__(256) d3_k(
    const float* __restrict__ X,
    const float* __restrict__ w,
    const float* __restrict__ bias,
    float* __restrict__ out)
{
    __shared__ __align__(16) float ws[64][16];
    const int tid = threadIdx.x;
    for (int i = tid; i < 1024; i += 256) ws[i >> 4][i & 15] = w[i];
    __syncthreads();

    const int b = blockIdx.y;
    const int u = blockIdx.x * 256 + tid;
    const int tbase = u * 16;
    if (tbase >= D3_LOUT) return;

    const float* xb = X + (size_t)b * 64 * D3_LIN;
    const int q0 = 2 * u;

    float acc[16];
#pragma unroll
    for (int i = 0; i < 16; i++) acc[i] = 0.f;

    for (int ci = 0; ci < 64; ci++) {
        const float* xr = xb + (size_t)ci * D3_LIN;
        float xA = (q0 - 1 >= 0)      ? xr[q0 - 1] : 0.f;
        float xB = (q0     < D3_LIN)  ? xr[q0]     : 0.f;
        float xC = (q0 + 1 < D3_LIN)  ? xr[q0 + 1] : 0.f;
        float xD = (q0 + 2 < D3_LIN)  ? xr[q0 + 2] : 0.f;
        const float4* w4 = reinterpret_cast<const float4*>(&ws[ci][0]);
        float4 w0 = w4[0], w1 = w4[1], w2 = w4[2], w3 = w4[3];
        float wv[16] = {w0.x,w0.y,w0.z,w0.w, w1.x,w1.y,w1.z,w1.w,
                        w2.x,w2.y,w2.z,w2.w, w3.x,w3.y,w3.z,w3.w};
#pragma unroll
        for (int tt = 0; tt < 4; tt++)
            acc[tt] = fmaf(wv[4 + tt], xB, fmaf(wv[12 + tt], xA, acc[tt]));
#pragma unroll
        for (int tt = 4; tt < 12; tt++)
            acc[tt] = fmaf(wv[tt - 4], xC, fmaf(wv[tt + 4], xB, acc[tt]));
#pragma unroll
        for (int tt = 12; tt < 16; tt++)
            acc[tt] = fmaf(wv[tt - 12], xD, fmaf(wv[tt - 4], xC, acc[tt]));
    }
    float b0 = bias[0];
    float* op = out + (size_t)b * D3_LOUT + tbase;
#pragma unroll
    for (int i = 0; i < 16; i++) {
        if (tbase + i < D3_LOUT) op[i] = tanhf(acc[i] + b0);
    }
}

__global__ void cnorm_k(const float* __restrict__ cbs, float* __restrict__ cn)
{
    int i = blockIdx.x * 256 + threadIdx.x;
    if (i < NBOOK * NCODE) {
        const float* r = cbs + (size_t)i * 128;
        float s = 0.f;
        for (int d = 0; d < 128; d++) s = __fmaf_rn(r[d], r[d], s);
        cn[i] = s;
    }
}

__global__ void pack_k(const int* __restrict__ codes, const float* __restrict__ part,
                       float* __restrict__ out)
{
    int i = blockIdx.x * 256 + threadIdx.x;
    if (i < CODES_SZ) out[X_OUT_SZ + i] = (float)codes[i];
    if (i == 0) {
        float s = 0.f;
        for (int j = 0; j < NBOOK * 63; j++) s += part[j];
        out[X_OUT_SZ + CODES_SZ] = 1.25f * s / (float)(BATCH * TLAT * 128);
    }
}

// ====================================================================
extern "C" void kernel_launch(void* const* d_in, const int* in_sizes, int n_in,
                              void* d_out, int out_size)
{
    const float* audio = (const float*)d_in[0];
    const float* ew[4] = {(const float*)d_in[1], (const float*)d_in[4],
                          (const float*)d_in[7], (const float*)d_in[10]};
    const float* eb[4] = {(const float*)d_in[2], (const float*)d_in[5],
                          (const float*)d_in[8], (const float*)d_in[11]};
    const float* ea[4] = {(const float*)d_in[3], (const float*)d_in[6],
                          (const float*)d_in[9], (const float*)d_in[12]};
    const float* dw[4] = {(const float*)d_in[13], (const float*)d_in[16],
                          (const float*)d_in[19], (const float*)d_in[22]};
    const float* db[4] = {(const float*)d_in[14], (const float*)d_in[17],
                          (const float*)d_in[20], (const float*)d_in[23]};
    const float* da[3] = {(const float*)d_in[15], (const float*)d_in[18],
                          (const float*)d_in[21]};
    const float* pin_w  = (const float*)d_in[24];
    const float* pin_b  = (const float*)d_in[25];
    const float* pout_w = (const float*)d_in[26];
    const float* pout_b = (const float*)d_in[27];
    const float* cbs    = (const float*)d_in[28];
    float* out = (float*)d_out;

    float *bufA, *bufB, *z, *res, *zp, *zq, *cn, *part, *pscore;
    int *codes, *pidx;
    cudaGetSymbolAddress((void**)&bufA,   g_bufA);
    cudaGetSymbolAddress((void**)&bufB,   g_bufB);
    cudaGetSymbolAddress((void**)&z,      g_z);
    cudaGetSymbolAddress((void**)&res,    g_res);
    cudaGetSymbolAddress((void**)&zp,     g_zp);
    cudaGetSymbolAddress((void**)&zq,     g_zq);
    cudaGetSymbolAddress((void**)&cn,     g_cnorm);
    cudaGetSymbolAddress((void**)&part,   g_part);
    cudaGetSymbolAddress((void**)&codes,  g_codes);
    cudaGetSymbolAddress((void**)&pscore, g_pscore);
    cudaGetSymbolAddress((void**)&pidx,   g_pidx);

    cnorm_k<<<(NBOOK * NCODE + 255) / 256, 256>>>(cbs, cn);

    // ---------------- encoder (bit-exact fp32 path) ----------------
    e0_k<<<dim3(118, 64), 256>>>(audio, ew[0], eb[0], ea[0], bufA);
    gemm_big_k<1, 2, 10, 5, 2><<<dim3(24, 1, 64), 256>>>(
        ew[1], bufA, eb[1], nullptr, ea[1], bufB, nullptr, 128, 640, 2999, 15000, 64);
    gemm_big_k<1, 2, 8, 4, 2><<<dim3(6, 2, 64), 256>>>(
        ew[2], bufB, eb[2], nullptr, ea[2], bufA, nullptr, 256, 1024, 749, 2999, 128);
    gemm_big_k<1, 2, 6, 3, 1><<<dim3(2, 4, 64), 256>>>(
        ew[3], bufA, eb[3], nullptr, ea[3], z, nullptr, 512, 1536, 249, 749, 256);

    // ---------------- residual VQ (codes bit-exact) ----------------
    for (int bk = 0; bk < NBOOK; bk++) {
        const float* cb  = cbs + (size_t)bk * NCODE * 128;
        const float* src = (bk == 0) ? z : res;
        gemm_big_k<0, 1, 1, 1, 0><<<dim3(2, 1, 64), 256>>>(
            pin_w, src, pin_b, nullptr, nullptr, zp, nullptr, 128, 512, TLAT, 0, 0);
        vq_gemm_argmin_k<<<dim3(2, 8, 64), 256>>>(
            cb, zp, cn + bk * NCODE, pscore, pidx);
        vq_finish_k<<<63, 256>>>(pscore, pidx, cb, zp, bk, codes, zq, part);
        if (bk == 0)
            gemm_big_k<0, 4, 1, 1, 0><<<dim3(2, 4, 64), 256>>>(
                pout_w, zq, pout_b, z, nullptr, res, nullptr, 512, 128, TLAT, 0, 0);
        else if (bk < NBOOK - 1)
            gemm_big_k<0, 3, 1, 1, 0><<<dim3(2, 4, 64), 256>>>(
                pout_w, zq, pout_b, nullptr, nullptr, res, nullptr, 512, 128, TLAT, 0, 0);
        else  // last book: fused res-update + z_q = fl(z - fl(res - v)) -> z
            gemm_big_k<0, 5, 1, 1, 0><<<dim3(2, 4, 64), 256>>>(
                pout_w, zq, pout_b, z, nullptr, res, z, 512, 128, TLAT, 0, 0);
    }

    // ---------------- decoder (FP16 tensor cores, direct W layout) ----
    dec_mma_k<1><<<dim3(2, 12, 64), 256>>>(dw[0], z, bufB, 1536, 512, 249);
    {
        size_t tot = (size_t)BATCH * 256 * 748;
        convt_gather_k<<<(unsigned)((tot + 255) / 256), 256>>>(
            bufB, db[0], da[0], bufA, 256, 6, 3, 1, 249, 748);
    }
    dec_mma_k<1><<<dim3(6, 8, 64), 256>>>(dw[1], bufA, bufB, 1024, 256, 748);
    {
        size_t tot = (size_t)BATCH * 128 * 2992;
        convt_gather_k<<<(unsigned)((tot + 255) / 256), 256>>>(
            bufB, db[1], da[1], bufA, 128, 8, 4, 2, 748, 2992);
    }
    dec_mma_k<1><<<dim3(24, 5, 64), 256>>>(dw[2], bufA, bufB, 640, 128, 2992);
    {
        size_t tot = (size_t)BATCH * 64 * 14961;
        convt_gather_k<<<(unsigned)((tot + 255) / 256), 256>>>(
            bufB, db[2], da[2], bufA, 64, 10, 5, 2, 2992, 14961);
    }
    d3_k<<<dim3(30, 64), 256>>>(bufA, dw[3], db[3], out);

    // ---------------- codes + vq_loss tail ----------------
    if (out_size >= FULL_OUT)
        pack_k<<<(CODES_SZ + 255) / 256, 256>>>(codes, part, out);
}